// round 3
// baseline (speedup 1.0000x reference)
#include <cuda_runtime.h>
#include <cuda_bf16.h>
#include <math.h>

// Problem constants
// B=16, N=300, U=100, V=200, E=128, H=8, hd=16, L=3
// adj: [16,100,200] bool (dtype widened by harness -> sniffed at runtime)
// weights: [16,100,200] f32
// W_layers: [3,8,16,16], a_layers: [3,8,32], W_last: [128,257]
// out: [16, 20000, 128] f32

#define NEGV (-9000000000000000.0f)

// Scratch (allocation-free: device globals)
__device__ float g_bufA[16 * 38400];
__device__ float g_bufB[16 * 38400];
__device__ float g_pu[16 * 100 * 128];
__device__ float g_pv[16 * 200 * 128];
__device__ unsigned char g_adj[16 * 20000];
__device__ int g_adjmode;   // 0 = int32, 1 = uint8, 2 = float32

// ---------------------------------------------------------------------------
// adj dtype sniffing + canonicalization to uint8 (deterministic, data-driven)
// ---------------------------------------------------------------------------
__global__ void detect_adj_kernel(const unsigned int* __restrict__ a)
{
    __shared__ int sf32, smulti;
    if (threadIdx.x == 0) { sf32 = 0; smulti = 0; }
    __syncthreads();
    // Scan 80000 words: safe for the smallest candidate (u8: 320000 B).
    for (int i = threadIdx.x; i < 80000; i += 256) {
        unsigned int v = a[i];
        if (v == 0x3F800000u) atomicOr(&sf32, 1);
        else if (v != 0u && v != 1u) atomicOr(&smulti, 1);
    }
    __syncthreads();
    if (threadIdx.x == 0)
        g_adjmode = sf32 ? 2 : (smulti ? 1 : 0);
}

__global__ void convert_adj_kernel(const void* __restrict__ a,
                                   unsigned char* __restrict__ dst)
{
    int i = blockIdx.x * 256 + threadIdx.x;
    if (i >= 320000) return;
    int mode = g_adjmode;
    unsigned char v;
    if (mode == 0)      v = (((const int*)a)[i] != 0);
    else if (mode == 1) v = (((const unsigned char*)a)[i] != 0);
    else                v = (((const float*)a)[i] != 0.0f);
    dst[i] = v;
}

// ---------------------------------------------------------------------------
// GAT layer: one CTA per (b, head). 256 threads.
// smem layout (floats):
//   [0,4800)      sWh   Wh[300][16]
//   [4800,9600)   sh    h input [300][16]
//   [9600,9856)   sWt   W transposed [k][j] 16x16
//   [9856,9872)   sa1
//   [9872,9888)   sa2
//   [9888,10188)  se1[300]
//   [10188,10488) se2[300]
//   [10488,15488) sadj (20000 bytes)
//   [15488,22016) sattb [8 warps][4 rows][204]
// total 22016 floats = 88064 bytes
// ---------------------------------------------------------------------------
__global__ void __launch_bounds__(256, 1) gat_layer_kernel(
    const float* __restrict__ hin,
    const unsigned char* __restrict__ adj,
    const float* __restrict__ Wl,   // [8][16][16]
    const float* __restrict__ al,   // [8][32]
    float* __restrict__ hout)
{
    extern __shared__ float sm[];
    float* sWh = sm;
    float* sh  = sm + 4800;
    float* sWt = sm + 9600;
    float* sa1 = sm + 9856;
    float* sa2 = sm + 9872;
    float* se1 = sm + 9888;
    float* se2 = sm + 10188;
    unsigned char* sadj = (unsigned char*)(sm + 10488);
    float* sattb = sm + 15488;

    const int tid  = threadIdx.x;
    const int lane = tid & 31;
    const int w    = tid >> 5;
    const int b    = blockIdx.x >> 3;
    const int hh   = blockIdx.x & 7;

    const float* hsrc = hin + (b * 8 + hh) * 4800;
    float* hdst = hout + (b * 8 + hh) * 4800;
    const unsigned char* A = adj + b * 20000;
    const float* W = Wl + hh * 256;
    const float* a = al + hh * 32;

    // ---- loads ----
    for (int i = tid; i < 1200; i += 256)
        ((float4*)sh)[i] = ((const float4*)hsrc)[i];
    for (int i = tid; i < 1250; i += 256)
        ((uint4*)sadj)[i] = ((const uint4*)A)[i];
    {
        int j = tid >> 4, k = tid & 15;
        sWt[k * 16 + j] = W[tid];          // transpose: sWt[k][j] = W[j][k]
    }
    if (tid < 16) { sa1[tid] = a[tid]; sa2[tid] = a[16 + tid]; }
    __syncthreads();

    // ---- Wh = h @ W^T, plus e1 = Wh.a1, e2 = Wh.a2 ----
    for (int base = tid; base < 4800; base += 256) {
        int n = base >> 4, jj = base & 15;
        const float* hr = sh + n * 16;
        float s = 0.f;
        #pragma unroll
        for (int k = 0; k < 16; k++) s = fmaf(hr[k], sWt[k * 16 + jj], s);
        sWh[base] = s;
        float p1 = s * sa1[jj];
        float p2 = s * sa2[jj];
        #pragma unroll
        for (int off = 8; off; off >>= 1) {
            p1 += __shfl_xor_sync(0xffffffffu, p1, off);
            p2 += __shfl_xor_sync(0xffffffffu, p2, off);
        }
        if (jj == 0) { se1[n] = p1; se2[n] = p2; }
    }
    __syncthreads();

    // ---- 75 row groups of 4: groups 0..24 = attU (rows u), 25..74 = attV (rows v)
    for (int g = w; g < 75; g += 8) {
        const bool modeU  = (g < 25);
        const int  r0     = modeU ? (g << 2) : ((g - 25) << 2);
        const int  L      = modeU ? 200 : 100;
        const int  accBase = modeU ? 100 : 0;

        float vals[4][7];
        float m[4];
        #pragma unroll
        for (int r = 0; r < 4; r++) m[r] = -1e30f;

        #pragma unroll
        for (int k = 0; k < 7; k++) {
            int idx = lane + (k << 5);
            bool act = idx < L;
            #pragma unroll
            for (int r = 0; r < 4; r++) {
                float e = -1e30f;
                if (act) {
                    unsigned char ad;
                    float t;
                    if (modeU) {
                        ad = sadj[(r0 + r) * 200 + idx];
                        t  = se1[r0 + r] + se2[100 + idx];
                    } else {
                        ad = sadj[idx * 200 + (r0 + r)];
                        t  = se1[idx] + se2[100 + r0 + r];
                    }
                    t = (t > 0.f) ? t : 0.01f * t;   // leaky_relu
                    e = ad ? NEGV : t;
                }
                vals[r][k] = e;
                m[r] = fmaxf(m[r], e);
            }
        }

        float selfe[4];
        #pragma unroll
        for (int r = 0; r < 4; r++) {
            int sn = modeU ? (r0 + r) : (100 + r0 + r);
            float t = se1[sn] + se2[sn];
            t = (t > 0.f) ? t : 0.01f * t;
            selfe[r] = t;
            m[r] = fmaxf(m[r], t);
        }
        #pragma unroll
        for (int off = 16; off; off >>= 1) {
            #pragma unroll
            for (int r = 0; r < 4; r++)
                m[r] = fmaxf(m[r], __shfl_xor_sync(0xffffffffu, m[r], off));
        }

        float ssum[4] = {0.f, 0.f, 0.f, 0.f};
        #pragma unroll
        for (int k = 0; k < 7; k++) {
            #pragma unroll
            for (int r = 0; r < 4; r++) {
                float ev = __expf(vals[r][k] - m[r]);
                vals[r][k] = ev;
                ssum[r] += ev;
            }
        }
        #pragma unroll
        for (int off = 16; off; off >>= 1) {
            #pragma unroll
            for (int r = 0; r < 4; r++)
                ssum[r] += __shfl_xor_sync(0xffffffffu, ssum[r], off);
        }

        float aself[4], inv[4];
        #pragma unroll
        for (int r = 0; r < 4; r++) {
            float es = __expf(selfe[r] - m[r]);
            float d  = ssum[r] + es;
            inv[r]   = 1.f / d;
            aself[r] = es * inv[r];
        }

        float* ab = sattb + ((w << 2) * 204);
        #pragma unroll
        for (int k = 0; k < 7; k++) {
            int idx = lane + (k << 5);
            if (idx < L) {
                #pragma unroll
                for (int r = 0; r < 4; r++)
                    ab[r * 204 + idx] = vals[r][k] * inv[r];
            }
        }
        __syncwarp();

        // accumulate: lane = (v4, q); each Wh float4 read feeds 16 FMAs
        const int q = lane & 3, v4 = lane >> 2;
        float4 acc[4];
        #pragma unroll
        for (int r = 0; r < 4; r++) acc[r] = make_float4(0.f, 0.f, 0.f, 0.f);

        for (int i = v4; i < L; i += 8) {
            float4 w4 = *(const float4*)&sWh[(accBase + i) * 16 + (q << 2)];
            #pragma unroll
            for (int r = 0; r < 4; r++) {
                float av = ab[r * 204 + i];
                acc[r].x = fmaf(av, w4.x, acc[r].x);
                acc[r].y = fmaf(av, w4.y, acc[r].y);
                acc[r].z = fmaf(av, w4.z, acc[r].z);
                acc[r].w = fmaf(av, w4.w, acc[r].w);
            }
        }
        #pragma unroll
        for (int off = 4; off < 32; off <<= 1) {
            #pragma unroll
            for (int r = 0; r < 4; r++) {
                acc[r].x += __shfl_xor_sync(0xffffffffu, acc[r].x, off);
                acc[r].y += __shfl_xor_sync(0xffffffffu, acc[r].y, off);
                acc[r].z += __shfl_xor_sync(0xffffffffu, acc[r].z, off);
                acc[r].w += __shfl_xor_sync(0xffffffffu, acc[r].w, off);
            }
        }
        if (v4 == 0) {
            #pragma unroll
            for (int r = 0; r < 4; r++) {
                int node = modeU ? (r0 + r) : (100 + r0 + r);
                float4 ws = *(const float4*)&sWh[node * 16 + (q << 2)];
                float4 res;
                res.x = acc[r].x + aself[r] * ws.x;
                res.y = acc[r].y + aself[r] * ws.y;
                res.z = acc[r].z + aself[r] * ws.z;
                res.w = acc[r].w + aself[r] * ws.w;
                // elu
                res.x = (res.x > 0.f) ? res.x : expm1f(res.x);
                res.y = (res.y > 0.f) ? res.y : expm1f(res.y);
                res.z = (res.z > 0.f) ? res.z : expm1f(res.z);
                res.w = (res.w > 0.f) ? res.w : expm1f(res.w);
                *(float4*)&hdst[node * 16 + (q << 2)] = res;
            }
        }
        __syncwarp();
    }
}

// ---------------------------------------------------------------------------
// pu = hE[:, :U] @ W1^T ; pv = hE[:, U:] @ W2^T
// grid: 16 b * 15 tiles of 20 nodes (tiles 0..4: U with W1, 5..14: V with W2)
// smem: hsm[20][132] + Wsm[128][132]  (pad 132 avoids bank conflicts)
// ---------------------------------------------------------------------------
__global__ void __launch_bounds__(256, 1) pupv_kernel(
    const float* __restrict__ hE,     // [16][38400]
    const float* __restrict__ Wlast,  // [128][257]
    float* __restrict__ pu, float* __restrict__ pv)
{
    extern __shared__ float sm[];
    float* hsm = sm;           // 20*132 = 2640
    float* Wsm = sm + 2640;    // 128*132 = 16896

    const int blk = blockIdx.x;
    const int b = blk / 15, t = blk % 15;
    const bool isU = (t < 5);
    const int n0 = isU ? t * 20 : 100 + (t - 5) * 20;
    const int coff = isU ? 0 : 128;
    const int tid = threadIdx.x;

    for (int i = tid; i < 128 * 128; i += 256) {
        int e = i >> 7, k = i & 127;
        Wsm[e * 132 + k] = Wlast[e * 257 + coff + k];
    }
    for (int i = tid; i < 20 * 128; i += 256) {
        int n = i >> 7, k = i & 127;
        hsm[n * 132 + k] = hE[b * 38400 + (n0 + n) * 128 + k];
    }
    __syncthreads();

    const int e = tid & 127, half = tid >> 7;
    float acc[10];
    #pragma unroll
    for (int n = 0; n < 10; n++) acc[n] = 0.f;
    const float* wrow  = Wsm + e * 132;
    const float* hbase = hsm + (half * 10) * 132;

    #pragma unroll 8
    for (int k4 = 0; k4 < 32; k4++) {
        float4 wv = *(const float4*)&wrow[k4 * 4];
        #pragma unroll
        for (int n = 0; n < 10; n++) {
            float4 hv = *(const float4*)&hbase[n * 132 + k4 * 4];
            acc[n] = fmaf(wv.x, hv.x, acc[n]);
            acc[n] = fmaf(wv.y, hv.y, acc[n]);
            acc[n] = fmaf(wv.z, hv.z, acc[n]);
            acc[n] = fmaf(wv.w, hv.w, acc[n]);
        }
    }
    int nodeBase = isU ? (b * 100 + n0 + half * 10) : (b * 200 + (n0 - 100) + half * 10);
    float* dst = isU ? (pu + (size_t)nodeBase * 128) : (pv + (size_t)nodeBase * 128);
    #pragma unroll
    for (int n = 0; n < 10; n++) dst[n * 128 + e] = acc[n];
}

// ---------------------------------------------------------------------------
// out[b,u,v,:] = mask*(pu[b,u,:] + pv[b,v,:]) + weights[b,u,v]*wl
// grid: 16 b * 10 u-groups of 10. pv[b] cached in smem (102.4 KB).
// ---------------------------------------------------------------------------
__global__ void __launch_bounds__(256, 1) out_kernel(
    const float* __restrict__ pu, const float* __restrict__ pv,
    const unsigned char* __restrict__ adj, const float* __restrict__ weights,
    const float* __restrict__ Wlast, float* __restrict__ out)
{
    extern __shared__ float sm[];
    float* spv = sm;            // 200*128 = 25600
    float* spu = sm + 25600;    // 10*128 = 1280
    float* swl = sm + 26880;    // 128

    const int b = blockIdx.x / 10, ug = blockIdx.x % 10;
    const int u0 = ug * 10;
    const int tid = threadIdx.x, lane = tid & 31, w = tid >> 5;

    for (int i = tid; i < 6400; i += 256)
        ((float4*)spv)[i] = ((const float4*)(pv + b * 25600))[i];
    for (int i = tid; i < 320; i += 256)
        ((float4*)spu)[i] = ((const float4*)(pu + (b * 100 + u0) * 128))[i];
    if (tid < 128) swl[tid] = Wlast[tid * 257 + 256];
    __syncthreads();

    const float4 wl4 = *(const float4*)&swl[lane * 4];
    for (int iu = 0; iu < 10; iu++) {
        const int u = u0 + iu;
        const unsigned char* arow = adj + (b * 100 + u) * 200;
        const float* wrow = weights + (b * 100 + u) * 200;
        const float4 pu4 = *(const float4*)&spu[iu * 128 + lane * 4];
        float* obase = out + ((size_t)(b * 100 + u)) * 200 * 128;
        for (int v = w; v < 200; v += 8) {
            const float msk = arow[v] ? 0.f : 1.f;
            const float wt  = wrow[v];
            const float4 pv4 = *(const float4*)&spv[v * 128 + lane * 4];
            float4 o;
            o.x = msk * (pu4.x + pv4.x) + wt * wl4.x;
            o.y = msk * (pu4.y + pv4.y) + wt * wl4.y;
            o.z = msk * (pu4.z + pv4.z) + wt * wl4.z;
            o.w = msk * (pu4.w + pv4.w) + wt * wl4.w;
            *(float4*)&obase[(size_t)v * 128 + lane * 4] = o;
        }
    }
}

// ---------------------------------------------------------------------------
extern "C" void kernel_launch(void* const* d_in, const int* in_sizes, int n_in,
                              void* d_out, int out_size)
{
    (void)in_sizes; (void)n_in; (void)out_size;
    const float* x              = (const float*)d_in[0];
    const void*  adj_raw        = (const void*)d_in[1];
    const float* weights        = (const float*)d_in[2];
    const float* Wlayers        = (const float*)d_in[3];
    const float* alayers        = (const float*)d_in[4];
    const float* Wlast          = (const float*)d_in[5];
    float* out = (float*)d_out;

    float *dA, *dB, *dpu, *dpv;
    unsigned char* dadj;
    cudaGetSymbolAddress((void**)&dA, g_bufA);
    cudaGetSymbolAddress((void**)&dB, g_bufB);
    cudaGetSymbolAddress((void**)&dpu, g_pu);
    cudaGetSymbolAddress((void**)&dpv, g_pv);
    cudaGetSymbolAddress((void**)&dadj, g_adj);

    const int SM1 = 22016 * 4;                  // 88064
    const int SM2 = (2640 + 128 * 132) * 4;     // 78144
    const int SM3 = 27008 * 4;                  // 108032
    cudaFuncSetAttribute(gat_layer_kernel, cudaFuncAttributeMaxDynamicSharedMemorySize, SM1);
    cudaFuncSetAttribute(pupv_kernel,      cudaFuncAttributeMaxDynamicSharedMemorySize, SM2);
    cudaFuncSetAttribute(out_kernel,       cudaFuncAttributeMaxDynamicSharedMemorySize, SM3);

    detect_adj_kernel<<<1, 256>>>((const unsigned int*)adj_raw);
    convert_adj_kernel<<<(320000 + 255) / 256, 256>>>(adj_raw, dadj);

    gat_layer_kernel<<<128, 256, SM1>>>(x,  dadj, Wlayers,        alayers,       dA);
    gat_layer_kernel<<<128, 256, SM1>>>(dA, dadj, Wlayers + 2048, alayers + 256, dB);
    gat_layer_kernel<<<128, 256, SM1>>>(dB, dadj, Wlayers + 4096, alayers + 512, dA);
    pupv_kernel<<<240, 256, SM2>>>(dA, Wlast, dpu, dpv);
    out_kernel<<<160, 256, SM3>>>(dpu, dpv, dadj, weights, Wlast, out);
}

// round 5
// speedup vs baseline: 2.6565x; 2.6565x over previous
#include <cuda_runtime.h>
#include <cuda_bf16.h>
#include <math.h>

// B=16, N=300, U=100, V=200, E=128, H=8, hd=16, L=3
// out: [16, 20000, 128] f32 (163.8 MB)

#define NEGV (-9000000000000000.0f)

// Scratch (allocation-free: device globals)
__device__ float g_bufA[16 * 38400];
__device__ float g_bufB[16 * 38400];
__device__ float g_pu[16 * 100 * 128];
__device__ float g_pv[16 * 200 * 128];
__device__ unsigned char g_adj[16 * 20000];
__device__ int g_f32flag;
__device__ int g_multiflag;

// ---------------------------------------------------------------------------
// adj dtype sniffing (parallel) + canonicalization to uint8
// ---------------------------------------------------------------------------
__global__ void detect_init_kernel() { g_f32flag = 0; g_multiflag = 0; }

__global__ void detect_adj_kernel(const unsigned int* __restrict__ a)
{
    int f32 = 0, multi = 0;
    for (int i = blockIdx.x * blockDim.x + threadIdx.x; i < 80000;
         i += gridDim.x * blockDim.x) {
        unsigned int v = a[i];
        if (v == 0x3F800000u) f32 = 1;
        else if (v != 0u && v != 1u) multi = 1;
    }
    if (f32)   atomicOr(&g_f32flag, 1);
    if (multi) atomicOr(&g_multiflag, 1);
}

__global__ void convert_adj_kernel(const void* __restrict__ a,
                                   unsigned char* __restrict__ dst)
{
    int i = blockIdx.x * 256 + threadIdx.x;
    if (i >= 320000) return;
    int mode = g_f32flag ? 2 : (g_multiflag ? 1 : 0);
    unsigned char v;
    if (mode == 0)      v = (((const int*)a)[i] != 0);
    else if (mode == 1) v = (((const unsigned char*)a)[i] != 0);
    else                v = (((const float*)a)[i] != 0.0f);
    dst[i] = v;
}

// ---------------------------------------------------------------------------
// GAT layer: one CTA per (b, head). 512 threads (16 warps).
// smem layout (floats):
//   [0,4800)      sWh    Wh[300][16]
//   [4800,5056)   sWt    W transposed [k][j] 16x16
//   [5056,5072)   sa1
//   [5072,5088)   sa2
//   [5088,5388)   se1[300]
//   [5388,5688)   se2[300]
//   [5688,10688)  sadj   (20000 bytes)
//   [10688,23744) sattb  [16 warps][4 rows][204]   (sh aliased on top)
// total 23744 floats = 94976 bytes
// ---------------------------------------------------------------------------
#define GAT_THREADS 512

__global__ void __launch_bounds__(GAT_THREADS, 1) gat_layer_kernel(
    const float* __restrict__ hin,
    const unsigned char* __restrict__ adj,
    const float* __restrict__ Wl,   // [8][16][16]
    const float* __restrict__ al,   // [8][32]
    float* __restrict__ hout)
{
    extern __shared__ float sm[];
    float* sWh = sm;
    float* sWt = sm + 4800;
    float* sa1 = sm + 5056;
    float* sa2 = sm + 5072;
    float* se1 = sm + 5088;
    float* se2 = sm + 5388;
    unsigned char* sadj = (unsigned char*)(sm + 5688);
    float* sattb = sm + 10688;
    float* sh    = sm + 10688;   // alias: used only before sattb phase

    const int tid  = threadIdx.x;
    const int lane = tid & 31;
    const int w    = tid >> 5;
    const int b    = blockIdx.x >> 3;
    const int hh   = blockIdx.x & 7;

    const float* hsrc = hin + (b * 8 + hh) * 4800;
    float* hdst = hout + (b * 8 + hh) * 4800;
    const unsigned char* A = adj + b * 20000;
    const float* W = Wl + hh * 256;
    const float* a = al + hh * 32;

    // ---- loads ----
    for (int i = tid; i < 1200; i += GAT_THREADS)
        ((float4*)sh)[i] = ((const float4*)hsrc)[i];
    for (int i = tid; i < 1250; i += GAT_THREADS)
        ((uint4*)sadj)[i] = ((const uint4*)A)[i];
    if (tid < 256) {
        int j = tid >> 4, k = tid & 15;
        sWt[k * 16 + j] = W[tid];          // transpose: sWt[k][j] = W[j][k]
    }
    if (tid < 16) { sa1[tid] = a[tid]; sa2[tid] = a[16 + tid]; }
    __syncthreads();

    // ---- Wh = h @ W^T, e1 = Wh.a1, e2 = Wh.a2 ----
    for (int base = tid; base < 4800; base += GAT_THREADS) {
        int n = base >> 4, jj = base & 15;
        const float* hr = sh + n * 16;
        float s = 0.f;
        #pragma unroll
        for (int k = 0; k < 16; k++) s = fmaf(hr[k], sWt[k * 16 + jj], s);
        sWh[base] = s;
        float p1 = s * sa1[jj];
        float p2 = s * sa2[jj];
        #pragma unroll
        for (int off = 8; off; off >>= 1) {
            p1 += __shfl_xor_sync(0xffffffffu, p1, off);
            p2 += __shfl_xor_sync(0xffffffffu, p2, off);
        }
        if (jj == 0) { se1[n] = p1; se2[n] = p2; }
    }
    __syncthreads();   // also protects sh -> sattb alias reuse

    // ---- 75 row groups of 4: groups 0..24 = attU (rows u), 25..74 = attV ----
    for (int g = w; g < 75; g += 16) {
        const bool modeU  = (g < 25);
        const int  r0     = modeU ? (g << 2) : ((g - 25) << 2);
        const int  L      = modeU ? 200 : 100;
        const int  accBase = modeU ? 100 : 0;

        float vals[4][7];
        float m[4];
        #pragma unroll
        for (int r = 0; r < 4; r++) m[r] = -1e30f;

        #pragma unroll
        for (int k = 0; k < 7; k++) {
            int idx = lane + (k << 5);
            bool act = idx < L;
            #pragma unroll
            for (int r = 0; r < 4; r++) {
                float e = -1e30f;
                if (act) {
                    unsigned char ad;
                    float t;
                    if (modeU) {
                        ad = sadj[(r0 + r) * 200 + idx];
                        t  = se1[r0 + r] + se2[100 + idx];
                    } else {
                        ad = sadj[idx * 200 + (r0 + r)];
                        t  = se1[idx] + se2[100 + r0 + r];
                    }
                    t = (t > 0.f) ? t : 0.01f * t;   // leaky_relu
                    e = ad ? NEGV : t;
                }
                vals[r][k] = e;
                m[r] = fmaxf(m[r], e);
            }
        }

        float selfe[4];
        #pragma unroll
        for (int r = 0; r < 4; r++) {
            int sn = modeU ? (r0 + r) : (100 + r0 + r);
            float t = se1[sn] + se2[sn];
            t = (t > 0.f) ? t : 0.01f * t;
            selfe[r] = t;
            m[r] = fmaxf(m[r], t);
        }
        #pragma unroll
        for (int off = 16; off; off >>= 1) {
            #pragma unroll
            for (int r = 0; r < 4; r++)
                m[r] = fmaxf(m[r], __shfl_xor_sync(0xffffffffu, m[r], off));
        }

        float ssum[4] = {0.f, 0.f, 0.f, 0.f};
        #pragma unroll
        for (int k = 0; k < 7; k++) {
            #pragma unroll
            for (int r = 0; r < 4; r++) {
                float ev = __expf(vals[r][k] - m[r]);
                vals[r][k] = ev;
                ssum[r] += ev;
            }
        }
        #pragma unroll
        for (int off = 16; off; off >>= 1) {
            #pragma unroll
            for (int r = 0; r < 4; r++)
                ssum[r] += __shfl_xor_sync(0xffffffffu, ssum[r], off);
        }

        float aself[4], inv[4];
        #pragma unroll
        for (int r = 0; r < 4; r++) {
            float es = __expf(selfe[r] - m[r]);
            float d  = ssum[r] + es;
            inv[r]   = 1.f / d;
            aself[r] = es * inv[r];
        }

        float* ab = sattb + ((w << 2) * 204);
        #pragma unroll
        for (int k = 0; k < 7; k++) {
            int idx = lane + (k << 5);
            if (idx < L) {
                #pragma unroll
                for (int r = 0; r < 4; r++)
                    ab[r * 204 + idx] = vals[r][k] * inv[r];
            }
        }
        __syncwarp();

        // accumulate: lane = (v4, q); each Wh float4 read feeds 16 FMAs
        const int q = lane & 3, v4 = lane >> 2;
        float4 acc[4];
        #pragma unroll
        for (int r = 0; r < 4; r++) acc[r] = make_float4(0.f, 0.f, 0.f, 0.f);

        for (int i = v4; i < L; i += 8) {
            float4 w4 = *(const float4*)&sWh[(accBase + i) * 16 + (q << 2)];
            #pragma unroll
            for (int r = 0; r < 4; r++) {
                float av = ab[r * 204 + i];
                acc[r].x = fmaf(av, w4.x, acc[r].x);
                acc[r].y = fmaf(av, w4.y, acc[r].y);
                acc[r].z = fmaf(av, w4.z, acc[r].z);
                acc[r].w = fmaf(av, w4.w, acc[r].w);
            }
        }
        #pragma unroll
        for (int off = 4; off < 32; off <<= 1) {
            #pragma unroll
            for (int r = 0; r < 4; r++) {
                acc[r].x += __shfl_xor_sync(0xffffffffu, acc[r].x, off);
                acc[r].y += __shfl_xor_sync(0xffffffffu, acc[r].y, off);
                acc[r].z += __shfl_xor_sync(0xffffffffu, acc[r].z, off);
                acc[r].w += __shfl_xor_sync(0xffffffffu, acc[r].w, off);
            }
        }
        if (v4 == 0) {
            #pragma unroll
            for (int r = 0; r < 4; r++) {
                int node = modeU ? (r0 + r) : (100 + r0 + r);
                float4 ws = *(const float4*)&sWh[node * 16 + (q << 2)];
                float4 res;
                res.x = acc[r].x + aself[r] * ws.x;
                res.y = acc[r].y + aself[r] * ws.y;
                res.z = acc[r].z + aself[r] * ws.z;
                res.w = acc[r].w + aself[r] * ws.w;
                res.x = (res.x > 0.f) ? res.x : expm1f(res.x);
                res.y = (res.y > 0.f) ? res.y : expm1f(res.y);
                res.z = (res.z > 0.f) ? res.z : expm1f(res.z);
                res.w = (res.w > 0.f) ? res.w : expm1f(res.w);
                *(float4*)&hdst[node * 16 + (q << 2)] = res;
            }
        }
        __syncwarp();
    }
}

// ---------------------------------------------------------------------------
// pu = hE[:, :U] @ W1^T ; pv = hE[:, U:] @ W2^T
// grid: 16 b * 15 tiles of 20 nodes
// ---------------------------------------------------------------------------
__global__ void __launch_bounds__(256, 1) pupv_kernel(
    const float* __restrict__ hE,     // [16][38400]
    const float* __restrict__ Wlast,  // [128][257]
    float* __restrict__ pu, float* __restrict__ pv)
{
    extern __shared__ float sm[];
    float* hsm = sm;           // 20*132 = 2640
    float* Wsm = sm + 2640;    // 128*132 = 16896

    const int blk = blockIdx.x;
    const int b = blk / 15, t = blk % 15;
    const bool isU = (t < 5);
    const int n0 = isU ? t * 20 : 100 + (t - 5) * 20;
    const int coff = isU ? 0 : 128;
    const int tid = threadIdx.x;

    for (int i = tid; i < 128 * 128; i += 256) {
        int e = i >> 7, k = i & 127;
        Wsm[e * 132 + k] = Wlast[e * 257 + coff + k];
    }
    for (int i = tid; i < 20 * 128; i += 256) {
        int n = i >> 7, k = i & 127;
        hsm[n * 132 + k] = hE[b * 38400 + (n0 + n) * 128 + k];
    }
    __syncthreads();

    const int e = tid & 127, half = tid >> 7;
    float acc[10];
    #pragma unroll
    for (int n = 0; n < 10; n++) acc[n] = 0.f;
    const float* wrow  = Wsm + e * 132;
    const float* hbase = hsm + (half * 10) * 132;

    #pragma unroll 8
    for (int k4 = 0; k4 < 32; k4++) {
        float4 wv = *(const float4*)&wrow[k4 * 4];
        #pragma unroll
        for (int n = 0; n < 10; n++) {
            float4 hv = *(const float4*)&hbase[n * 132 + k4 * 4];
            acc[n] = fmaf(wv.x, hv.x, acc[n]);
            acc[n] = fmaf(wv.y, hv.y, acc[n]);
            acc[n] = fmaf(wv.z, hv.z, acc[n]);
            acc[n] = fmaf(wv.w, hv.w, acc[n]);
        }
    }
    int nodeBase = isU ? (b * 100 + n0 + half * 10) : (b * 200 + (n0 - 100) + half * 10);
    float* dst = isU ? (pu + (size_t)nodeBase * 128) : (pv + (size_t)nodeBase * 128);
    #pragma unroll
    for (int n = 0; n < 10; n++) dst[n * 128 + e] = acc[n];
}

// ---------------------------------------------------------------------------
// out[b,u,v,:] = mask*(pu[b,u,:] + pv[b,v,:]) + weights[b,u,v]*wl
// grid: 16 b * 9 balanced u-slices (11 or 12 rows) = 144 CTAs (single wave)
// ---------------------------------------------------------------------------
__global__ void __launch_bounds__(256, 1) out_kernel(
    const float* __restrict__ pu, const float* __restrict__ pv,
    const unsigned char* __restrict__ adj, const float* __restrict__ weights,
    const float* __restrict__ Wlast, float* __restrict__ out)
{
    extern __shared__ float sm[];
    float* spv = sm;            // 200*128 = 25600
    float* spu = sm + 25600;    // up to 12*128 = 1536
    float* swl = sm + 27136;    // 128

    const int b = blockIdx.x / 9, gslice = blockIdx.x % 9;
    const int u0 = (gslice * 100) / 9;
    const int u1 = ((gslice + 1) * 100) / 9;
    const int nu = u1 - u0;
    const int tid = threadIdx.x, lane = tid & 31, w = tid >> 5;

    for (int i = tid; i < 6400; i += 256)
        ((float4*)spv)[i] = ((const float4*)(pv + b * 25600))[i];
    for (int i = tid; i < nu * 32; i += 256)
        ((float4*)spu)[i] = ((const float4*)(pu + (b * 100 + u0) * 128))[i];
    if (tid < 128) swl[tid] = Wlast[tid * 257 + 256];
    __syncthreads();

    const float4 wl4 = *(const float4*)&swl[lane * 4];
    for (int iu = 0; iu < nu; iu++) {
        const int u = u0 + iu;
        const unsigned char* arow = adj + (b * 100 + u) * 200;
        const float* wrow = weights + (b * 100 + u) * 200;
        const float4 pu4 = *(const float4*)&spu[iu * 128 + lane * 4];
        float* obase = out + ((size_t)(b * 100 + u)) * 200 * 128;
        for (int v = w; v < 200; v += 8) {
            const float msk = arow[v] ? 0.f : 1.f;
            const float wt  = wrow[v];
            const float4 pv4 = *(const float4*)&spv[v * 128 + lane * 4];
            float4 o;
            o.x = msk * (pu4.x + pv4.x) + wt * wl4.x;
            o.y = msk * (pu4.y + pv4.y) + wt * wl4.y;
            o.z = msk * (pu4.z + pv4.z) + wt * wl4.z;
            o.w = msk * (pu4.w + pv4.w) + wt * wl4.w;
            *(float4*)&obase[(size_t)v * 128 + lane * 4] = o;
        }
    }
}

// ---------------------------------------------------------------------------
extern "C" void kernel_launch(void* const* d_in, const int* in_sizes, int n_in,
                              void* d_out, int out_size)
{
    (void)in_sizes; (void)n_in; (void)out_size;
    const float* x              = (const float*)d_in[0];
    const void*  adj_raw        = (const void*)d_in[1];
    const float* weights        = (const float*)d_in[2];
    const float* Wlayers        = (const float*)d_in[3];
    const float* alayers        = (const float*)d_in[4];
    const float* Wlast          = (const float*)d_in[5];
    float* out = (float*)d_out;

    float *dA, *dB, *dpu, *dpv;
    unsigned char* dadj;
    cudaGetSymbolAddress((void**)&dA, g_bufA);
    cudaGetSymbolAddress((void**)&dB, g_bufB);
    cudaGetSymbolAddress((void**)&dpu, g_pu);
    cudaGetSymbolAddress((void**)&dpv, g_pv);
    cudaGetSymbolAddress((void**)&dadj, g_adj);

    const int SM1 = 23744 * 4;                  // 94976
    const int SM2 = (2640 + 128 * 132) * 4;     // 78144
    const int SM3 = (27136 + 128) * 4;          // 109056
    cudaFuncSetAttribute(gat_layer_kernel, cudaFuncAttributeMaxDynamicSharedMemorySize, SM1);
    cudaFuncSetAttribute(pupv_kernel,      cudaFuncAttributeMaxDynamicSharedMemorySize, SM2);
    cudaFuncSetAttribute(out_kernel,       cudaFuncAttributeMaxDynamicSharedMemorySize, SM3);

    detect_init_kernel<<<1, 1>>>();
    detect_adj_kernel<<<80, 256>>>((const unsigned int*)adj_raw);
    convert_adj_kernel<<<(320000 + 255) / 256, 256>>>(adj_raw, dadj);

    gat_layer_kernel<<<128, GAT_THREADS, SM1>>>(x,  dadj, Wlayers,        alayers,       dA);
    gat_layer_kernel<<<128, GAT_THREADS, SM1>>>(dA, dadj, Wlayers + 2048, alayers + 256, dB);
    gat_layer_kernel<<<128, GAT_THREADS, SM1>>>(dB, dadj, Wlayers + 4096, alayers + 512, dA);
    pupv_kernel<<<240, 256, SM2>>>(dA, Wlast, dpu, dpv);
    out_kernel<<<144, 256, SM3>>>(dpu, dpv, dadj, weights, Wlast, out);
}

// round 6
// speedup vs baseline: 3.1481x; 1.1851x over previous
#include <cuda_runtime.h>
#include <cuda_bf16.h>
#include <math.h>

// B=16, N=300, U=100, V=200, E=128, H=8, hd=16, L=3
// out: [16, 20000, 128] f32 (163.8 MB)

#define NEGV (-9000000000000000.0f)

// Scratch (allocation-free: device globals)
__device__ float g_hE[16 * 38400];
__device__ float g_pu[16 * 100 * 128];
__device__ float g_pv[16 * 200 * 128];
__device__ unsigned char g_adj[16 * 20000];
__device__ int g_f32flag;
__device__ int g_multiflag;

// ---------------------------------------------------------------------------
// adj dtype sniffing (parallel) + canonicalization to uint8
// ---------------------------------------------------------------------------
__global__ void detect_init_kernel() { g_f32flag = 0; g_multiflag = 0; }

__global__ void detect_adj_kernel(const unsigned int* __restrict__ a)
{
    int f32 = 0, multi = 0;
    for (int i = blockIdx.x * blockDim.x + threadIdx.x; i < 80000;
         i += gridDim.x * blockDim.x) {
        unsigned int v = a[i];
        if (v == 0x3F800000u) f32 = 1;
        else if (v != 0u && v != 1u) multi = 1;
    }
    if (f32)   atomicOr(&g_f32flag, 1);
    if (multi) atomicOr(&g_multiflag, 1);
}

__global__ void convert_adj_kernel(const void* __restrict__ a,
                                   unsigned char* __restrict__ dst)
{
    int i = blockIdx.x * 256 + threadIdx.x;
    if (i >= 320000) return;
    int mode = g_f32flag ? 2 : (g_multiflag ? 1 : 0);
    unsigned char v;
    if (mode == 0)      v = (((const int*)a)[i] != 0);
    else if (mode == 1) v = (((const unsigned char*)a)[i] != 0);
    else                v = (((const float*)a)[i] != 0.0f);
    dst[i] = v;
}

// ---------------------------------------------------------------------------
// Fused 3-layer GAT: one CTA per (b, head). 768 threads (24 warps).
// (b,h) chains are independent across layers (vmap over heads, out_axes=1).
// smem layout (floats):
//   [0,4800)      sWh    Wh[300][16]
//   [4800,9600)   shh    persistent h [300][16]
//   [9600,9856)   sWt    W transposed 16x16
//   [9856,9872)   sa1
//   [9872,9888)   sa2
//   [9888,10188)  se1[300]
//   [10188,10488) se2[300]
//   [10488,15488) sadj   (20000 bytes)
//   [15488,35072) sattb  [24 warps][4 rows][204]
// total 35072 floats = 140288 bytes -> 1 CTA/SM, 24 warps
// ---------------------------------------------------------------------------
#define GAT_THREADS 768

__global__ void __launch_bounds__(GAT_THREADS, 1) gat_fused_kernel(
    const float* __restrict__ hin,
    const unsigned char* __restrict__ adj,
    const float* __restrict__ Wl,   // [3][8][16][16]
    const float* __restrict__ al,   // [3][8][32]
    float* __restrict__ hout)
{
    extern __shared__ float sm[];
    float* sWh = sm;
    float* shh = sm + 4800;
    float* sWt = sm + 9600;
    float* sa1 = sm + 9856;
    float* sa2 = sm + 9872;
    float* se1 = sm + 9888;
    float* se2 = sm + 10188;
    unsigned char* sadj = (unsigned char*)(sm + 10488);
    float* sattb = sm + 15488;

    const int tid  = threadIdx.x;
    const int lane = tid & 31;
    const int w    = tid >> 5;
    const int b    = blockIdx.x >> 3;
    const int hh   = blockIdx.x & 7;

    const float* hsrc = hin + (b * 8 + hh) * 4800;
    float* hdst = hout + (b * 8 + hh) * 4800;
    const unsigned char* A = adj + b * 20000;

    // ---- one-time loads ----
    for (int i = tid; i < 1200; i += GAT_THREADS)
        ((float4*)shh)[i] = ((const float4*)hsrc)[i];
    for (int i = tid; i < 1250; i += GAT_THREADS)
        ((uint4*)sadj)[i] = ((const uint4*)A)[i];

    for (int l = 0; l < 3; l++) {
        const float* W = Wl + (l * 8 + hh) * 256;
        const float* a = al + (l * 8 + hh) * 32;
        if (tid < 256) {
            int j = tid >> 4, k = tid & 15;
            sWt[k * 16 + j] = W[tid];      // sWt[k][j] = W[j][k]
        }
        if (tid < 16) { sa1[tid] = a[tid]; sa2[tid] = a[16 + tid]; }
        __syncthreads();

        // ---- Wh = h @ W^T, e1 = Wh.a1, e2 = Wh.a2 ----
        for (int base = tid; base < 4800; base += GAT_THREADS) {
            int n = base >> 4, jj = base & 15;
            const float* hr = shh + n * 16;
            float s = 0.f;
            #pragma unroll
            for (int k = 0; k < 16; k++) s = fmaf(hr[k], sWt[k * 16 + jj], s);
            sWh[base] = s;
            float p1 = s * sa1[jj];
            float p2 = s * sa2[jj];
            #pragma unroll
            for (int off = 8; off; off >>= 1) {
                p1 += __shfl_xor_sync(0xffffffffu, p1, off);
                p2 += __shfl_xor_sync(0xffffffffu, p2, off);
            }
            if (jj == 0) { se1[n] = p1; se2[n] = p2; }
        }
        __syncthreads();

        // ---- attention: 75 groups of 4 rows. Groups 0..24 = attU (cost ~2),
        //      25..74 = attV (cost ~1). LPT schedule caps a warp at 5 units. ----
        for (int k = 0; k < 4; k++) {
            int g;
            if (k == 0)      g = w;                                   // U0..U23
            else if (k == 1) g = (w == 3) ? 24
                               : (25 + w - (w > 3 ? 1 : 0));          // U24 / V25..47
            else if (k == 2) g = 48 + w;                              // V48..71
            else { if (w >= 3) break; g = 72 + w; }                   // V72..74

            const bool modeU   = (g < 25);
            const int  r0      = modeU ? (g << 2) : ((g - 25) << 2);
            const int  L       = modeU ? 200 : 100;
            const int  accBase = modeU ? 100 : 0;

            float vals[4][7];
            float m[4];
            #pragma unroll
            for (int r = 0; r < 4; r++) m[r] = -1e30f;

            #pragma unroll
            for (int kk = 0; kk < 7; kk++) {
                int idx = lane + (kk << 5);
                bool act = idx < L;
                #pragma unroll
                for (int r = 0; r < 4; r++) {
                    float e = -1e30f;
                    if (act) {
                        unsigned char ad;
                        float t;
                        if (modeU) {
                            ad = sadj[(r0 + r) * 200 + idx];
                            t  = se1[r0 + r] + se2[100 + idx];
                        } else {
                            ad = sadj[idx * 200 + (r0 + r)];
                            t  = se1[idx] + se2[100 + r0 + r];
                        }
                        t = (t > 0.f) ? t : 0.01f * t;   // leaky_relu
                        e = ad ? NEGV : t;
                    }
                    vals[r][kk] = e;
                    m[r] = fmaxf(m[r], e);
                }
            }

            float selfe[4];
            #pragma unroll
            for (int r = 0; r < 4; r++) {
                int sn = modeU ? (r0 + r) : (100 + r0 + r);
                float t = se1[sn] + se2[sn];
                t = (t > 0.f) ? t : 0.01f * t;
                selfe[r] = t;
                m[r] = fmaxf(m[r], t);
            }
            #pragma unroll
            for (int off = 16; off; off >>= 1) {
                #pragma unroll
                for (int r = 0; r < 4; r++)
                    m[r] = fmaxf(m[r], __shfl_xor_sync(0xffffffffu, m[r], off));
            }

            float ssum[4] = {0.f, 0.f, 0.f, 0.f};
            #pragma unroll
            for (int kk = 0; kk < 7; kk++) {
                #pragma unroll
                for (int r = 0; r < 4; r++) {
                    float ev = __expf(vals[r][kk] - m[r]);
                    vals[r][kk] = ev;
                    ssum[r] += ev;
                }
            }
            #pragma unroll
            for (int off = 16; off; off >>= 1) {
                #pragma unroll
                for (int r = 0; r < 4; r++)
                    ssum[r] += __shfl_xor_sync(0xffffffffu, ssum[r], off);
            }

            float aself[4], inv[4];
            #pragma unroll
            for (int r = 0; r < 4; r++) {
                float es = __expf(selfe[r] - m[r]);
                float d  = ssum[r] + es;
                inv[r]   = 1.f / d;
                aself[r] = es * inv[r];
            }

            float* ab = sattb + ((w << 2) * 204);
            #pragma unroll
            for (int kk = 0; kk < 7; kk++) {
                int idx = lane + (kk << 5);
                if (idx < L) {
                    #pragma unroll
                    for (int r = 0; r < 4; r++)
                        ab[r * 204 + idx] = vals[r][kk] * inv[r];
                }
            }
            __syncwarp();

            // accumulate: lane = (v4, q); each Wh float4 read feeds 16 FMAs
            const int q = lane & 3, v4 = lane >> 2;
            float4 acc[4];
            #pragma unroll
            for (int r = 0; r < 4; r++) acc[r] = make_float4(0.f, 0.f, 0.f, 0.f);

            for (int i = v4; i < L; i += 8) {
                float4 w4 = *(const float4*)&sWh[(accBase + i) * 16 + (q << 2)];
                #pragma unroll
                for (int r = 0; r < 4; r++) {
                    float av = ab[r * 204 + i];
                    acc[r].x = fmaf(av, w4.x, acc[r].x);
                    acc[r].y = fmaf(av, w4.y, acc[r].y);
                    acc[r].z = fmaf(av, w4.z, acc[r].z);
                    acc[r].w = fmaf(av, w4.w, acc[r].w);
                }
            }
            #pragma unroll
            for (int off = 4; off < 32; off <<= 1) {
                #pragma unroll
                for (int r = 0; r < 4; r++) {
                    acc[r].x += __shfl_xor_sync(0xffffffffu, acc[r].x, off);
                    acc[r].y += __shfl_xor_sync(0xffffffffu, acc[r].y, off);
                    acc[r].z += __shfl_xor_sync(0xffffffffu, acc[r].z, off);
                    acc[r].w += __shfl_xor_sync(0xffffffffu, acc[r].w, off);
                }
            }
            if (v4 == 0) {
                #pragma unroll
                for (int r = 0; r < 4; r++) {
                    int node = modeU ? (r0 + r) : (100 + r0 + r);
                    float4 ws = *(const float4*)&sWh[node * 16 + (q << 2)];
                    float4 res;
                    res.x = acc[r].x + aself[r] * ws.x;
                    res.y = acc[r].y + aself[r] * ws.y;
                    res.z = acc[r].z + aself[r] * ws.z;
                    res.w = acc[r].w + aself[r] * ws.w;
                    res.x = (res.x > 0.f) ? res.x : expm1f(res.x);
                    res.y = (res.y > 0.f) ? res.y : expm1f(res.y);
                    res.z = (res.z > 0.f) ? res.z : expm1f(res.z);
                    res.w = (res.w > 0.f) ? res.w : expm1f(res.w);
                    if (l == 2)
                        *(float4*)&hdst[node * 16 + (q << 2)] = res;
                    else
                        *(float4*)&shh[node * 16 + (q << 2)] = res;
                }
            }
            __syncwarp();
        }
        __syncthreads();   // shh fully written before next layer's Wh phase
    }
}

// ---------------------------------------------------------------------------
// pu = hE[:, :U] @ W1^T ; pv = hE[:, U:] @ W2^T
// grid: 16 b * 15 tiles of 20 nodes
// ---------------------------------------------------------------------------
__global__ void __launch_bounds__(256, 1) pupv_kernel(
    const float* __restrict__ hE,     // [16][38400]
    const float* __restrict__ Wlast,  // [128][257]
    float* __restrict__ pu, float* __restrict__ pv)
{
    extern __shared__ float sm[];
    float* hsm = sm;           // 20*132 = 2640
    float* Wsm = sm + 2640;    // 128*132 = 16896

    const int blk = blockIdx.x;
    const int b = blk / 15, t = blk % 15;
    const bool isU = (t < 5);
    const int n0 = isU ? t * 20 : 100 + (t - 5) * 20;
    const int coff = isU ? 0 : 128;
    const int tid = threadIdx.x;

    for (int i = tid; i < 128 * 128; i += 256) {
        int e = i >> 7, k = i & 127;
        Wsm[e * 132 + k] = Wlast[e * 257 + coff + k];
    }
    for (int i = tid; i < 20 * 128; i += 256) {
        int n = i >> 7, k = i & 127;
        hsm[n * 132 + k] = hE[b * 38400 + (n0 + n) * 128 + k];
    }
    __syncthreads();

    const int e = tid & 127, half = tid >> 7;
    float acc[10];
    #pragma unroll
    for (int n = 0; n < 10; n++) acc[n] = 0.f;
    const float* wrow  = Wsm + e * 132;
    const float* hbase = hsm + (half * 10) * 132;

    #pragma unroll 8
    for (int k4 = 0; k4 < 32; k4++) {
        float4 wv = *(const float4*)&wrow[k4 * 4];
        #pragma unroll
        for (int n = 0; n < 10; n++) {
            float4 hv = *(const float4*)&hbase[n * 132 + k4 * 4];
            acc[n] = fmaf(wv.x, hv.x, acc[n]);
            acc[n] = fmaf(wv.y, hv.y, acc[n]);
            acc[n] = fmaf(wv.z, hv.z, acc[n]);
            acc[n] = fmaf(wv.w, hv.w, acc[n]);
        }
    }
    int nodeBase = isU ? (b * 100 + n0 + half * 10) : (b * 200 + (n0 - 100) + half * 10);
    float* dst = isU ? (pu + (size_t)nodeBase * 128) : (pv + (size_t)nodeBase * 128);
    #pragma unroll
    for (int n = 0; n < 10; n++) dst[n * 128 + e] = acc[n];
}

// ---------------------------------------------------------------------------
// out[b,u,v,:] = mask*(pu[b,u,:] + pv[b,v,:]) + weights[b,u,v]*wl
// grid: 16 b * 9 balanced u-slices = 144 CTAs (single wave), 512 threads
// ---------------------------------------------------------------------------
__global__ void __launch_bounds__(512, 1) out_kernel(
    const float* __restrict__ pu, const float* __restrict__ pv,
    const unsigned char* __restrict__ adj, const float* __restrict__ weights,
    const float* __restrict__ Wlast, float* __restrict__ out)
{
    extern __shared__ float sm[];
    float* spv = sm;            // 200*128 = 25600
    float* spu = sm + 25600;    // up to 12*128 = 1536
    float* swl = sm + 27136;    // 128

    const int b = blockIdx.x / 9, gslice = blockIdx.x % 9;
    const int u0 = (gslice * 100) / 9;
    const int u1 = ((gslice + 1) * 100) / 9;
    const int nu = u1 - u0;
    const int tid = threadIdx.x, lane = tid & 31, w = tid >> 5;

    for (int i = tid; i < 6400; i += 512)
        ((float4*)spv)[i] = ((const float4*)(pv + b * 25600))[i];
    for (int i = tid; i < nu * 32; i += 512)
        ((float4*)spu)[i] = ((const float4*)(pu + (b * 100 + u0) * 128))[i];
    if (tid < 128) swl[tid] = Wlast[tid * 257 + 256];
    __syncthreads();

    const float4 wl4 = *(const float4*)&swl[lane * 4];
    for (int iu = 0; iu < nu; iu++) {
        const int u = u0 + iu;
        const unsigned char* arow = adj + (b * 100 + u) * 200;
        const float* wrow = weights + (b * 100 + u) * 200;
        const float4 pu4 = *(const float4*)&spu[iu * 128 + lane * 4];
        float* obase = out + ((size_t)(b * 100 + u)) * 200 * 128;
        for (int v = w; v < 200; v += 16) {
            const float msk = arow[v] ? 0.f : 1.f;
            const float wt  = wrow[v];
            const float4 pv4 = *(const float4*)&spv[v * 128 + lane * 4];
            float4 o;
            o.x = msk * (pu4.x + pv4.x) + wt * wl4.x;
            o.y = msk * (pu4.y + pv4.y) + wt * wl4.y;
            o.z = msk * (pu4.z + pv4.z) + wt * wl4.z;
            o.w = msk * (pu4.w + pv4.w) + wt * wl4.w;
            *(float4*)&obase[(size_t)v * 128 + lane * 4] = o;
        }
    }
}

// ---------------------------------------------------------------------------
extern "C" void kernel_launch(void* const* d_in, const int* in_sizes, int n_in,
                              void* d_out, int out_size)
{
    (void)in_sizes; (void)n_in; (void)out_size;
    const float* x              = (const float*)d_in[0];
    const void*  adj_raw        = (const void*)d_in[1];
    const float* weights        = (const float*)d_in[2];
    const float* Wlayers        = (const float*)d_in[3];
    const float* alayers        = (const float*)d_in[4];
    const float* Wlast          = (const float*)d_in[5];
    float* out = (float*)d_out;

    float *dH, *dpu, *dpv;
    unsigned char* dadj;
    cudaGetSymbolAddress((void**)&dH, g_hE);
    cudaGetSymbolAddress((void**)&dpu, g_pu);
    cudaGetSymbolAddress((void**)&dpv, g_pv);
    cudaGetSymbolAddress((void**)&dadj, g_adj);

    const int SM1 = 35072 * 4;                  // 140288
    const int SM2 = (2640 + 128 * 132) * 4;     // 78144
    const int SM3 = (27136 + 128) * 4;          // 109056
    cudaFuncSetAttribute(gat_fused_kernel, cudaFuncAttributeMaxDynamicSharedMemorySize, SM1);
    cudaFuncSetAttribute(pupv_kernel,      cudaFuncAttributeMaxDynamicSharedMemorySize, SM2);
    cudaFuncSetAttribute(out_kernel,       cudaFuncAttributeMaxDynamicSharedMemorySize, SM3);

    detect_init_kernel<<<1, 1>>>();
    detect_adj_kernel<<<80, 256>>>((const unsigned int*)adj_raw);
    convert_adj_kernel<<<(320000 + 255) / 256, 256>>>(adj_raw, dadj);

    gat_fused_kernel<<<128, GAT_THREADS, SM1>>>(x, dadj, Wlayers, alayers, dH);
    pupv_kernel<<<240, 256, SM2>>>(dH, Wlast, dpu, dpv);
    out_kernel<<<144, 512, SM3>>>(dpu, dpv, dadj, weights, Wlast, out);
}

// round 7
// speedup vs baseline: 3.1762x; 1.0089x over previous
#include <cuda_runtime.h>
#include <cuda_bf16.h>
#include <math.h>

// B=16, N=300, U=100, V=200, E=128, H=8, hd=16, L=3
// out: [16, 20000, 128] f32 (163.8 MB)

// Scratch (allocation-free: device globals)
__device__ float g_hE[16 * 38400];
__device__ float g_pu[16 * 100 * 128];
__device__ float g_pv[16 * 200 * 128];

// ---------------------------------------------------------------------------
// adj dtype detection, inlined in each consumer CTA.
// Scans the first 8192 32-bit words (covers the smallest candidate layout):
//   any word == 0x3F800000           -> float32 (impossible for 0/1 i32 or u8)
//   any word not in {0,1,0x3F800000} -> packed uint8 (certain within window)
//   else                             -> int32
// Deterministic, identical result in every CTA.
// ---------------------------------------------------------------------------
template <int NT>
__device__ __forceinline__ int detect_adj_mode(const void* adjraw, int* s_flags)
{
    const unsigned int* aw = (const unsigned int*)adjraw;
    int tid = threadIdx.x;
    if (tid == 0) { s_flags[0] = 0; s_flags[1] = 0; }
    __syncthreads();
    int f32 = 0, multi = 0;
    for (int i = tid; i < 8192; i += NT) {
        unsigned int v = aw[i];
        f32   |= (v == 0x3F800000u);
        multi |= (v != 0u && v != 1u && v != 0x3F800000u);
    }
    if (__any_sync(0xffffffffu, f32)   && (tid & 31) == 0) atomicOr(&s_flags[0], 1);
    if (__any_sync(0xffffffffu, multi) && (tid & 31) == 0) atomicOr(&s_flags[1], 1);
    __syncthreads();
    return s_flags[0] ? 2 : (s_flags[1] ? 1 : 0);   // 2=f32, 1=u8, 0=i32
}

// ---------------------------------------------------------------------------
// Fused 3-layer GAT: one CTA per (b, head). 768 threads (24 warps).
// smem layout (floats):
//   [0,4800)      sWh    Wh[300][16]
//   [4800,9600)   shh    persistent h [300][16]
//   [9600,9856)   sWt    W transposed 16x16
//   [9856,9872)   sa1
//   [9872,9888)   sa2
//   [9888,10188)  se1[300]
//   [10188,10488) se2[300]
//   [10488,15488) sadj   (20000 bytes, canonical u8)
//   [15488,35072) sattb  [24 warps][4 rows][204]
// total 35072 floats = 140288 bytes -> 1 CTA/SM, 24 warps
// ---------------------------------------------------------------------------
#define GAT_THREADS 768

__global__ void __launch_bounds__(GAT_THREADS, 1) gat_fused_kernel(
    const float* __restrict__ hin,
    const void*  __restrict__ adjraw,
    const float* __restrict__ Wl,   // [3][8][16][16]
    const float* __restrict__ al,   // [3][8][32]
    float* __restrict__ hout)
{
    extern __shared__ float sm[];
    float* sWh = sm;
    float* shh = sm + 4800;
    float* sWt = sm + 9600;
    float* sa1 = sm + 9856;
    float* sa2 = sm + 9872;
    float* se1 = sm + 9888;
    float* se2 = sm + 10188;
    unsigned char* sadj = (unsigned char*)(sm + 10488);
    float* sattb = sm + 15488;
    __shared__ int s_flags[2];

    const int tid  = threadIdx.x;
    const int lane = tid & 31;
    const int w    = tid >> 5;
    const int b    = blockIdx.x >> 3;
    const int hh   = blockIdx.x & 7;

    const float* hsrc = hin + (b * 8 + hh) * 4800;
    float* hdst = hout + (b * 8 + hh) * 4800;

    const int mode = detect_adj_mode<GAT_THREADS>(adjraw, s_flags);

    // ---- one-time loads ----
    for (int i = tid; i < 1200; i += GAT_THREADS)
        ((float4*)shh)[i] = ((const float4*)hsrc)[i];

    if (mode == 1) {
        const uint4* src = (const uint4*)((const unsigned char*)adjraw + b * 20000);
        for (int i = tid; i < 1250; i += GAT_THREADS)
            ((uint4*)sadj)[i] = src[i];
    } else if (mode == 0) {
        const int4* src = (const int4*)((const int*)adjraw + b * 20000);
        for (int i = tid; i < 5000; i += GAT_THREADS) {
            int4 v = src[i];
            ((uchar4*)sadj)[i] = make_uchar4(v.x != 0, v.y != 0, v.z != 0, v.w != 0);
        }
    } else {
        const float4* src = (const float4*)((const float*)adjraw + b * 20000);
        for (int i = tid; i < 5000; i += GAT_THREADS) {
            float4 v = src[i];
            ((uchar4*)sadj)[i] = make_uchar4(v.x != 0.f, v.y != 0.f, v.z != 0.f, v.w != 0.f);
        }
    }

    for (int l = 0; l < 3; l++) {
        const float* W = Wl + (l * 8 + hh) * 256;
        const float* a = al + (l * 8 + hh) * 32;
        if (tid < 256) {
            int j = tid >> 4, k = tid & 15;
            sWt[k * 16 + j] = W[tid];      // sWt[k][j] = W[j][k]
        }
        if (tid < 16) { sa1[tid] = a[tid]; sa2[tid] = a[16 + tid]; }
        __syncthreads();

        // ---- Wh = h @ W^T, e1 = Wh.a1, e2 = Wh.a2 ----
        for (int base = tid; base < 4800; base += GAT_THREADS) {
            int n = base >> 4, jj = base & 15;
            const float* hr = shh + n * 16;
            float s = 0.f;
            #pragma unroll
            for (int k = 0; k < 16; k++) s = fmaf(hr[k], sWt[k * 16 + jj], s);
            sWh[base] = s;
            float p1 = s * sa1[jj];
            float p2 = s * sa2[jj];
            #pragma unroll
            for (int off = 8; off; off >>= 1) {
                p1 += __shfl_xor_sync(0xffffffffu, p1, off);
                p2 += __shfl_xor_sync(0xffffffffu, p2, off);
            }
            if (jj == 0) { se1[n] = p1; se2[n] = p2; }
        }
        __syncthreads();

        // ---- attention: 75 groups of 4 rows. LPT schedule (U ~2x V cost). ----
        for (int k = 0; k < 4; k++) {
            int g;
            if (k == 0)      g = w;                                   // U0..U23
            else if (k == 1) g = (w == 3) ? 24
                               : (25 + w - (w > 3 ? 1 : 0));          // U24 / V25..47
            else if (k == 2) g = 48 + w;                              // V48..71
            else { if (w >= 3) break; g = 72 + w; }                   // V72..74

            const bool modeU = (g < 25);
            const int  r0    = modeU ? (g << 2) : ((g - 25) << 2);
            const int  L     = modeU ? 200 : 100;

            // per-row constants (uniform across lanes)
            float rowc[4], selfe[4];
            #pragma unroll
            for (int r = 0; r < 4; r++) {
                if (modeU) {
                    rowc[r]  = se1[r0 + r];
                    float t  = rowc[r] + se2[r0 + r];
                    selfe[r] = (t > 0.f) ? t : 0.01f * t;
                } else {
                    rowc[r]  = se2[100 + r0 + r];
                    float t  = se1[100 + r0 + r] + rowc[r];
                    selfe[r] = (t > 0.f) ? t : 0.01f * t;
                }
            }
            const float* colbase = modeU ? (se2 + 100) : se1;
            const unsigned char* adjU = sadj + r0 * 200;   // modeU rows
            const unsigned char* adjVc = sadj + r0;        // modeV: +idx*200

            // ---- scores -> exp(e - selfe[r]) (shift-invariant softmax, no max tree) ----
            float vals[4][7];
            float ssum[4] = {0.f, 0.f, 0.f, 0.f};
            #pragma unroll
            for (int kk = 0; kk < 7; kk++) {
                int idx = lane + (kk << 5);
                if (idx < L) {
                    float cv = colbase[idx];
                    const unsigned char* ac = adjVc + idx * 200;
                    #pragma unroll
                    for (int r = 0; r < 4; r++) {
                        unsigned char ad = modeU ? adjU[r * 200 + idx] : ac[r];
                        float t = rowc[r] + cv;
                        t = (t > 0.f) ? t : 0.01f * t;
                        float ev = ad ? 0.f : __expf(t - selfe[r]);
                        vals[r][kk] = ev;
                        ssum[r] += ev;
                    }
                } else {
                    #pragma unroll
                    for (int r = 0; r < 4; r++) vals[r][kk] = 0.f;
                }
            }
            #pragma unroll
            for (int off = 16; off; off >>= 1) {
                #pragma unroll
                for (int r = 0; r < 4; r++)
                    ssum[r] += __shfl_xor_sync(0xffffffffu, ssum[r], off);
            }

            float aself[4], inv[4];
            #pragma unroll
            for (int r = 0; r < 4; r++) {
                inv[r]   = 1.f / (ssum[r] + 1.f);   // self term: exp(0)=1
                aself[r] = inv[r];
            }

            float* ab = sattb + ((w << 2) * 204);
            #pragma unroll
            for (int kk = 0; kk < 7; kk++) {
                int idx = lane + (kk << 5);
                if (idx < L) {
                    #pragma unroll
                    for (int r = 0; r < 4; r++)
                        ab[r * 204 + idx] = vals[r][kk] * inv[r];
                }
            }
            __syncwarp();

            // ---- accumulate: lane = (v4, q); each Wh float4 feeds 16 FMAs ----
            const int q4 = (lane & 3) << 2, v4 = lane >> 2;
            float4 acc[4];
            #pragma unroll
            for (int r = 0; r < 4; r++) acc[r] = make_float4(0.f, 0.f, 0.f, 0.f);

            if (modeU) {
                const float* whb = sWh + 100 * 16 + q4;
                #pragma unroll 5
                for (int ii = 0; ii < 25; ii++) {
                    int i = v4 + (ii << 3);
                    float4 w4 = *(const float4*)&whb[i * 16];
                    #pragma unroll
                    for (int r = 0; r < 4; r++) {
                        float av = ab[r * 204 + i];
                        acc[r].x = fmaf(av, w4.x, acc[r].x);
                        acc[r].y = fmaf(av, w4.y, acc[r].y);
                        acc[r].z = fmaf(av, w4.z, acc[r].z);
                        acc[r].w = fmaf(av, w4.w, acc[r].w);
                    }
                }
            } else {
                const float* whb = sWh + q4;
                #pragma unroll 4
                for (int ii = 0; ii < 13; ii++) {
                    int i = v4 + (ii << 3);
                    if (i < 100) {
                        float4 w4 = *(const float4*)&whb[i * 16];
                        #pragma unroll
                        for (int r = 0; r < 4; r++) {
                            float av = ab[r * 204 + i];
                            acc[r].x = fmaf(av, w4.x, acc[r].x);
                            acc[r].y = fmaf(av, w4.y, acc[r].y);
                            acc[r].z = fmaf(av, w4.z, acc[r].z);
                            acc[r].w = fmaf(av, w4.w, acc[r].w);
                        }
                    }
                }
            }
            #pragma unroll
            for (int off = 4; off < 32; off <<= 1) {
                #pragma unroll
                for (int r = 0; r < 4; r++) {
                    acc[r].x += __shfl_xor_sync(0xffffffffu, acc[r].x, off);
                    acc[r].y += __shfl_xor_sync(0xffffffffu, acc[r].y, off);
                    acc[r].z += __shfl_xor_sync(0xffffffffu, acc[r].z, off);
                    acc[r].w += __shfl_xor_sync(0xffffffffu, acc[r].w, off);
                }
            }
            if (v4 == 0) {
                #pragma unroll
                for (int r = 0; r < 4; r++) {
                    int node = modeU ? (r0 + r) : (100 + r0 + r);
                    float4 ws = *(const float4*)&sWh[node * 16 + q4];
                    float4 res;
                    res.x = acc[r].x + aself[r] * ws.x;
                    res.y = acc[r].y + aself[r] * ws.y;
                    res.z = acc[r].z + aself[r] * ws.z;
                    res.w = acc[r].w + aself[r] * ws.w;
                    res.x = (res.x > 0.f) ? res.x : expm1f(res.x);
                    res.y = (res.y > 0.f) ? res.y : expm1f(res.y);
                    res.z = (res.z > 0.f) ? res.z : expm1f(res.z);
                    res.w = (res.w > 0.f) ? res.w : expm1f(res.w);
                    if (l == 2)
                        *(float4*)&hdst[node * 16 + q4] = res;
                    else
                        *(float4*)&shh[node * 16 + q4] = res;
                }
            }
            __syncwarp();
        }
        __syncthreads();   // shh fully written before next layer's Wh phase
    }
}

// ---------------------------------------------------------------------------
// pu = hE[:, :U] @ W1^T ; pv = hE[:, U:] @ W2^T
// grid: 16 b * 15 tiles of 20 nodes
// ---------------------------------------------------------------------------
__global__ void __launch_bounds__(256, 1) pupv_kernel(
    const float* __restrict__ hE,     // [16][38400]
    const float* __restrict__ Wlast,  // [128][257]
    float* __restrict__ pu, float* __restrict__ pv)
{
    extern __shared__ float sm[];
    float* hsm = sm;           // 20*132 = 2640
    float* Wsm = sm + 2640;    // 128*132 = 16896

    const int blk = blockIdx.x;
    const int b = blk / 15, t = blk % 15;
    const bool isU = (t < 5);
    const int n0 = isU ? t * 20 : 100 + (t - 5) * 20;
    const int coff = isU ? 0 : 128;
    const int tid = threadIdx.x;

    for (int i = tid; i < 128 * 128; i += 256) {
        int e = i >> 7, k = i & 127;
        Wsm[e * 132 + k] = Wlast[e * 257 + coff + k];
    }
    for (int i = tid; i < 20 * 128; i += 256) {
        int n = i >> 7, k = i & 127;
        hsm[n * 132 + k] = hE[b * 38400 + (n0 + n) * 128 + k];
    }
    __syncthreads();

    const int e = tid & 127, half = tid >> 7;
    float acc[10];
    #pragma unroll
    for (int n = 0; n < 10; n++) acc[n] = 0.f;
    const float* wrow  = Wsm + e * 132;
    const float* hbase = hsm + (half * 10) * 132;

    #pragma unroll 8
    for (int k4 = 0; k4 < 32; k4++) {
        float4 wv = *(const float4*)&wrow[k4 * 4];
        #pragma unroll
        for (int n = 0; n < 10; n++) {
            float4 hv = *(const float4*)&hbase[n * 132 + k4 * 4];
            acc[n] = fmaf(wv.x, hv.x, acc[n]);
            acc[n] = fmaf(wv.y, hv.y, acc[n]);
            acc[n] = fmaf(wv.z, hv.z, acc[n]);
            acc[n] = fmaf(wv.w, hv.w, acc[n]);
        }
    }
    int nodeBase = isU ? (b * 100 + n0 + half * 10) : (b * 200 + (n0 - 100) + half * 10);
    float* dst = isU ? (pu + (size_t)nodeBase * 128) : (pv + (size_t)nodeBase * 128);
    #pragma unroll
    for (int n = 0; n < 10; n++) dst[n * 128 + e] = acc[n];
}

// ---------------------------------------------------------------------------
// out[b,u,v,:] = mask*(pu[b,u,:] + pv[b,v,:]) + weights[b,u,v]*wl
// grid: 16 b * 9 balanced u-slices = 144 CTAs (single wave), 512 threads
// ---------------------------------------------------------------------------
__global__ void __launch_bounds__(512, 1) out_kernel(
    const float* __restrict__ pu, const float* __restrict__ pv,
    const void* __restrict__ adjraw, const float* __restrict__ weights,
    const float* __restrict__ Wlast, float* __restrict__ out)
{
    extern __shared__ float sm[];
    float* spv = sm;            // 200*128 = 25600
    float* spu = sm + 25600;    // up to 12*128 = 1536
    float* swl = sm + 27136;    // 128
    __shared__ int s_flags[2];

    const int b = blockIdx.x / 9, gslice = blockIdx.x % 9;
    const int u0 = (gslice * 100) / 9;
    const int u1 = ((gslice + 1) * 100) / 9;
    const int nu = u1 - u0;
    const int tid = threadIdx.x, lane = tid & 31, w = tid >> 5;

    const int mode = detect_adj_mode<512>(adjraw, s_flags);

    for (int i = tid; i < 6400; i += 512)
        ((float4*)spv)[i] = ((const float4*)(pv + b * 25600))[i];
    for (int i = tid; i < nu * 32; i += 512)
        ((float4*)spu)[i] = ((const float4*)(pu + (b * 100 + u0) * 128))[i];
    if (tid < 128) swl[tid] = Wlast[tid * 257 + 256];
    __syncthreads();

    const float4 wl4 = *(const float4*)&swl[lane * 4];
    for (int iu = 0; iu < nu; iu++) {
        const int u = u0 + iu;
        const int abase = (b * 100 + u) * 200;
        const float* wrow = weights + abase;
        const float4 pu4 = *(const float4*)&spu[iu * 128 + lane * 4];
        float* obase = out + ((size_t)(b * 100 + u)) * 200 * 128;
        for (int v = w; v < 200; v += 16) {
            float msk;
            if (mode == 0)      msk = ((const int*)adjraw)[abase + v] ? 0.f : 1.f;
            else if (mode == 1) msk = ((const unsigned char*)adjraw)[abase + v] ? 0.f : 1.f;
            else                msk = (((const float*)adjraw)[abase + v] != 0.f) ? 0.f : 1.f;
            const float wt  = wrow[v];
            const float4 pv4 = *(const float4*)&spv[v * 128 + lane * 4];
            float4 o;
            o.x = msk * (pu4.x + pv4.x) + wt * wl4.x;
            o.y = msk * (pu4.y + pv4.y) + wt * wl4.y;
            o.z = msk * (pu4.z + pv4.z) + wt * wl4.z;
            o.w = msk * (pu4.w + pv4.w) + wt * wl4.w;
            *(float4*)&obase[(size_t)v * 128 + lane * 4] = o;
        }
    }
}

// ---------------------------------------------------------------------------
extern "C" void kernel_launch(void* const* d_in, const int* in_sizes, int n_in,
                              void* d_out, int out_size)
{
    (void)in_sizes; (void)n_in; (void)out_size;
    const float* x              = (const float*)d_in[0];
    const void*  adj_raw        = (const void*)d_in[1];
    const float* weights        = (const float*)d_in[2];
    const float* Wlayers        = (const float*)d_in[3];
    const float* alayers        = (const float*)d_in[4];
    const float* Wlast          = (const float*)d_in[5];
    float* out = (float*)d_out;

    float *dH, *dpu, *dpv;
    cudaGetSymbolAddress((void**)&dH, g_hE);
    cudaGetSymbolAddress((void**)&dpu, g_pu);
    cudaGetSymbolAddress((void**)&dpv, g_pv);

    const int SM1 = 35072 * 4;                  // 140288
    const int SM2 = (2640 + 128 * 132) * 4;     // 78144
    const int SM3 = (27136 + 128) * 4;          // 109056
    cudaFuncSetAttribute(gat_fused_kernel, cudaFuncAttributeMaxDynamicSharedMemorySize, SM1);
    cudaFuncSetAttribute(pupv_kernel,      cudaFuncAttributeMaxDynamicSharedMemorySize, SM2);
    cudaFuncSetAttribute(out_kernel,       cudaFuncAttributeMaxDynamicSharedMemorySize, SM3);

    gat_fused_kernel<<<128, GAT_THREADS, SM1>>>(x, adj_raw, Wlayers, alayers, dH);
    pupv_kernel<<<240, 256, SM2>>>(dH, Wlast, dpu, dpv);
    out_kernel<<<144, 512, SM3>>>(dpu, dpv, adj_raw, weights, Wlast, out);
}

// round 8
// speedup vs baseline: 3.3369x; 1.0506x over previous
#include <cuda_runtime.h>
#include <cuda_bf16.h>
#include <math.h>

// B=16, N=300, U=100, V=200, E=128, H=8, hd=16, L=3
// out: [16, 20000, 128] f32 (163.8 MB)

// Scratch (allocation-free: device globals)
__device__ float g_hE[16 * 38400];
__device__ float g_pu[16 * 100 * 128];
__device__ float g_pv[16 * 200 * 128];

// ---------------------------------------------------------------------------
// adj dtype detection, inlined per consumer CTA. 2048-word window:
//   any word == 0x3F800000           -> float32
//   any word not in {0,1,0x3F800000} -> packed uint8 (p=0.3 -> certain)
//   else                             -> int32
// ---------------------------------------------------------------------------
template <int NT>
__device__ __forceinline__ int detect_adj_mode(const void* adjraw, int* s_flags)
{
    const unsigned int* aw = (const unsigned int*)adjraw;
    int tid = threadIdx.x;
    if (tid == 0) { s_flags[0] = 0; s_flags[1] = 0; }
    __syncthreads();
    int f32 = 0, multi = 0;
    #pragma unroll
    for (int i = tid; i < 2048; i += NT) {
        unsigned int v = aw[i];
        f32   |= (v == 0x3F800000u);
        multi |= (v != 0u && v != 1u && v != 0x3F800000u);
    }
    if (__any_sync(0xffffffffu, f32)   && (tid & 31) == 0) atomicOr(&s_flags[0], 1);
    if (__any_sync(0xffffffffu, multi) && (tid & 31) == 0) atomicOr(&s_flags[1], 1);
    __syncthreads();
    return s_flags[0] ? 2 : (s_flags[1] ? 1 : 0);   // 2=f32, 1=u8, 0=i32
}

// ---------------------------------------------------------------------------
// Fused 3-layer GAT: one CTA per (b, head). 768 threads (24 warps).
// smem floats:
//   [0,4800)      sWh   [300][16]
//   [4800,9600)   shh   persistent h [300][16]
//   [9600,9856)   sWt   16x16 transposed
//   [9856,9872)   sa1   [9872,9888) sa2
//   [9888,10188)  se1[300]   [10188,10488) se2[300]
//   [10488,15488) sadj (20000 B, canonical u8)
//   [15488,35072) sattb [24 warps][4][204]
// total 140288 bytes -> 1 CTA/SM
// ---------------------------------------------------------------------------
#define GAT_THREADS 768

__global__ void __launch_bounds__(GAT_THREADS, 1) gat_fused_kernel(
    const float* __restrict__ hin,
    const void*  __restrict__ adjraw,
    const float* __restrict__ Wl,   // [3][8][16][16]
    const float* __restrict__ al,   // [3][8][32]
    float* __restrict__ hout)
{
    extern __shared__ float sm[];
    float* sWh = sm;
    float* shh = sm + 4800;
    float* sWt = sm + 9600;
    float* sa1 = sm + 9856;
    float* sa2 = sm + 9872;
    float* se1 = sm + 9888;
    float* se2 = sm + 10188;
    unsigned char* sadj = (unsigned char*)(sm + 10488);
    float* sattb = sm + 15488;
    __shared__ int s_flags[2];

    const int tid  = threadIdx.x;
    const int lane = tid & 31;
    const int w    = tid >> 5;
    const int b    = blockIdx.x >> 3;
    const int hh   = blockIdx.x & 7;

    const float* hsrc = hin + (b * 8 + hh) * 4800;
    float* hdst = hout + (b * 8 + hh) * 4800;

    const int mode = detect_adj_mode<GAT_THREADS>(adjraw, s_flags);

    // ---- one-time loads ----
    for (int i = tid; i < 1200; i += GAT_THREADS)
        ((float4*)shh)[i] = ((const float4*)hsrc)[i];

    if (mode == 1) {
        const uint4* src = (const uint4*)((const unsigned char*)adjraw + b * 20000);
        for (int i = tid; i < 1250; i += GAT_THREADS)
            ((uint4*)sadj)[i] = src[i];
    } else if (mode == 0) {
        const int4* src = (const int4*)((const int*)adjraw + b * 20000);
        for (int i = tid; i < 5000; i += GAT_THREADS) {
            int4 v = src[i];
            ((uchar4*)sadj)[i] = make_uchar4(v.x != 0, v.y != 0, v.z != 0, v.w != 0);
        }
    } else {
        const float4* src = (const float4*)((const float*)adjraw + b * 20000);
        for (int i = tid; i < 5000; i += GAT_THREADS) {
            float4 v = src[i];
            ((uchar4*)sadj)[i] = make_uchar4(v.x != 0.f, v.y != 0.f, v.z != 0.f, v.w != 0.f);
        }
    }

    for (int l = 0; l < 3; l++) {
        const float* W = Wl + (l * 8 + hh) * 256;
        const float* a = al + (l * 8 + hh) * 32;
        if (tid < 256) {
            int j = tid >> 4, k = tid & 15;
            sWt[k * 16 + j] = W[tid];      // sWt[k][j] = W[j][k]
        }
        if (tid < 16) { sa1[tid] = a[tid]; sa2[tid] = a[16 + tid]; }
        __syncthreads();

        // ---- Wh = h @ W^T, e1 = Wh.a1, e2 = Wh.a2 ----
        for (int base = tid; base < 4800; base += GAT_THREADS) {
            int n = base >> 4, jj = base & 15;
            const float* hr = shh + n * 16;
            float s = 0.f;
            #pragma unroll
            for (int k = 0; k < 16; k++) s = fmaf(hr[k], sWt[k * 16 + jj], s);
            sWh[base] = s;
            float p1 = s * sa1[jj];
            float p2 = s * sa2[jj];
            #pragma unroll
            for (int off = 8; off; off >>= 1) {
                p1 += __shfl_xor_sync(0xffffffffu, p1, off);
                p2 += __shfl_xor_sync(0xffffffffu, p2, off);
            }
            if (jj == 0) { se1[n] = p1; se2[n] = p2; }
        }
        __syncthreads();

        // ---- attention: 75 groups of 4 rows, LPT schedule ----
        for (int k = 0; k < 4; k++) {
            int g;
            if (k == 0)      g = w;                                   // U0..U23
            else if (k == 1) g = (w == 3) ? 24
                               : (25 + w - (w > 3 ? 1 : 0));          // U24 / V25..47
            else if (k == 2) g = 48 + w;                              // V48..71
            else { if (w >= 3) break; g = 72 + w; }                   // V72..74

            const bool modeU = (g < 25);
            const int  r0    = modeU ? (g << 2) : ((g - 25) << 2);

            float* ab = sattb + ((w << 2) * 204);
            float rowc[4], selfe[4];
            float ssum[4] = {0.f, 0.f, 0.f, 0.f};

            if (modeU) {
                #pragma unroll
                for (int r = 0; r < 4; r++) {
                    rowc[r]  = se1[r0 + r];
                    float t  = rowc[r] + se2[r0 + r];
                    selfe[r] = (t > 0.f) ? t : 0.01f * t;
                }
                const float* cb = se2 + 100;
                const unsigned char* adjU = sadj + r0 * 200;
                #pragma unroll
                for (int kk = 0; kk < 6; kk++) {
                    int idx = lane + (kk << 5);
                    float cv = cb[idx];
                    #pragma unroll
                    for (int r = 0; r < 4; r++) {
                        float t = rowc[r] + cv;
                        t = (t > 0.f) ? t : 0.01f * t;
                        float ev = __expf(t - selfe[r]);
                        ev = adjU[r * 200 + idx] ? 0.f : ev;
                        ab[r * 204 + idx] = ev;
                        ssum[r] += ev;
                    }
                }
                if (lane < 8) {                    // tail: idx = 192+lane
                    int idx = 192 + lane;
                    float cv = cb[idx];
                    #pragma unroll
                    for (int r = 0; r < 4; r++) {
                        float t = rowc[r] + cv;
                        t = (t > 0.f) ? t : 0.01f * t;
                        float ev = __expf(t - selfe[r]);
                        ev = adjU[r * 200 + idx] ? 0.f : ev;
                        ab[r * 204 + idx] = ev;
                        ssum[r] += ev;
                    }
                }
            } else {
                #pragma unroll
                for (int r = 0; r < 4; r++) {
                    int node = 100 + r0 + r;
                    rowc[r]  = se2[node];
                    float t  = se1[node] + rowc[r];
                    selfe[r] = (t > 0.f) ? t : 0.01f * t;
                }
                const unsigned char* adjC = sadj + r0;
                #pragma unroll
                for (int kk = 0; kk < 3; kk++) {
                    int idx = lane + (kk << 5);
                    float cv = se1[idx];
                    unsigned int aw4 = *(const unsigned int*)(adjC + idx * 200);
                    #pragma unroll
                    for (int r = 0; r < 4; r++) {
                        float t = rowc[r] + cv;
                        t = (t > 0.f) ? t : 0.01f * t;
                        float ev = __expf(t - selfe[r]);
                        ev = ((aw4 >> (r * 8)) & 255u) ? 0.f : ev;
                        ab[r * 204 + idx] = ev;
                        ssum[r] += ev;
                    }
                }
                if (lane < 4) {                    // tail: idx = 96+lane
                    int idx = 96 + lane;
                    float cv = se1[idx];
                    unsigned int aw4 = *(const unsigned int*)(adjC + idx * 200);
                    #pragma unroll
                    for (int r = 0; r < 4; r++) {
                        float t = rowc[r] + cv;
                        t = (t > 0.f) ? t : 0.01f * t;
                        float ev = __expf(t - selfe[r]);
                        ev = ((aw4 >> (r * 8)) & 255u) ? 0.f : ev;
                        ab[r * 204 + idx] = ev;
                        ssum[r] += ev;
                    }
                }
            }
            __syncwarp();

            // ssum tree (independent of aggregation below -> latency overlapped)
            #pragma unroll
            for (int off = 16; off; off >>= 1) {
                #pragma unroll
                for (int r = 0; r < 4; r++)
                    ssum[r] += __shfl_xor_sync(0xffffffffu, ssum[r], off);
            }
            float inv[4];
            #pragma unroll
            for (int r = 0; r < 4; r++)
                inv[r] = 1.f / (ssum[r] + 1.f);    // self term exp(0)=1

            // ---- aggregation over raw ev; normalize at the end ----
            const int q4 = (lane & 3) << 2, v4 = lane >> 2;
            float4 acc[4];
            #pragma unroll
            for (int r = 0; r < 4; r++) acc[r] = make_float4(0.f, 0.f, 0.f, 0.f);

            if (modeU) {
                const float* whb = sWh + 100 * 16 + q4;
                #pragma unroll 5
                for (int ii = 0; ii < 25; ii++) {
                    int i = v4 + (ii << 3);
                    float4 w4 = *(const float4*)&whb[i * 16];
                    #pragma unroll
                    for (int r = 0; r < 4; r++) {
                        float av = ab[r * 204 + i];
                        acc[r].x = fmaf(av, w4.x, acc[r].x);
                        acc[r].y = fmaf(av, w4.y, acc[r].y);
                        acc[r].z = fmaf(av, w4.z, acc[r].z);
                        acc[r].w = fmaf(av, w4.w, acc[r].w);
                    }
                }
            } else {
                const float* whb = sWh + q4;
                #pragma unroll 4
                for (int ii = 0; ii < 13; ii++) {
                    int i = v4 + (ii << 3);
                    if (i < 100) {
                        float4 w4 = *(const float4*)&whb[i * 16];
                        #pragma unroll
                        for (int r = 0; r < 4; r++) {
                            float av = ab[r * 204 + i];
                            acc[r].x = fmaf(av, w4.x, acc[r].x);
                            acc[r].y = fmaf(av, w4.y, acc[r].y);
                            acc[r].z = fmaf(av, w4.z, acc[r].z);
                            acc[r].w = fmaf(av, w4.w, acc[r].w);
                        }
                    }
                }
            }
            #pragma unroll
            for (int off = 4; off < 32; off <<= 1) {
                #pragma unroll
                for (int r = 0; r < 4; r++) {
                    acc[r].x += __shfl_xor_sync(0xffffffffu, acc[r].x, off);
                    acc[r].y += __shfl_xor_sync(0xffffffffu, acc[r].y, off);
                    acc[r].z += __shfl_xor_sync(0xffffffffu, acc[r].z, off);
                    acc[r].w += __shfl_xor_sync(0xffffffffu, acc[r].w, off);
                }
            }
            if (v4 == 0) {
                #pragma unroll
                for (int r = 0; r < 4; r++) {
                    int node = modeU ? (r0 + r) : (100 + r0 + r);
                    float4 ws = *(const float4*)&sWh[node * 16 + q4];
                    float4 res;
                    res.x = (acc[r].x + ws.x) * inv[r];
                    res.y = (acc[r].y + ws.y) * inv[r];
                    res.z = (acc[r].z + ws.z) * inv[r];
                    res.w = (acc[r].w + ws.w) * inv[r];
                    res.x = (res.x > 0.f) ? res.x : expm1f(res.x);
                    res.y = (res.y > 0.f) ? res.y : expm1f(res.y);
                    res.z = (res.z > 0.f) ? res.z : expm1f(res.z);
                    res.w = (res.w > 0.f) ? res.w : expm1f(res.w);
                    if (l == 2)
                        *(float4*)&hdst[node * 16 + q4] = res;
                    else
                        *(float4*)&shh[node * 16 + q4] = res;
                }
            }
            __syncwarp();
        }
        __syncthreads();   // shh fully written before next layer's Wh phase
    }
}

// ---------------------------------------------------------------------------
// pu = hE[:, :U] @ W1^T ; pv = hE[:, U:] @ W2^T
// ---------------------------------------------------------------------------
__global__ void __launch_bounds__(256, 1) pupv_kernel(
    const float* __restrict__ hE,
    const float* __restrict__ Wlast,  // [128][257]
    float* __restrict__ pu, float* __restrict__ pv)
{
    extern __shared__ float sm[];
    float* hsm = sm;           // 20*132
    float* Wsm = sm + 2640;    // 128*132

    const int blk = blockIdx.x;
    const int b = blk / 15, t = blk % 15;
    const bool isU = (t < 5);
    const int n0 = isU ? t * 20 : 100 + (t - 5) * 20;
    const int coff = isU ? 0 : 128;
    const int tid = threadIdx.x;

    for (int i = tid; i < 128 * 128; i += 256) {
        int e = i >> 7, k = i & 127;
        Wsm[e * 132 + k] = Wlast[e * 257 + coff + k];
    }
    for (int i = tid; i < 20 * 128; i += 256) {
        int n = i >> 7, k = i & 127;
        hsm[n * 132 + k] = hE[b * 38400 + (n0 + n) * 128 + k];
    }
    __syncthreads();

    const int e = tid & 127, half = tid >> 7;
    float acc[10];
    #pragma unroll
    for (int n = 0; n < 10; n++) acc[n] = 0.f;
    const float* wrow  = Wsm + e * 132;
    const float* hbase = hsm + (half * 10) * 132;

    #pragma unroll 8
    for (int k4 = 0; k4 < 32; k4++) {
        float4 wv = *(const float4*)&wrow[k4 * 4];
        #pragma unroll
        for (int n = 0; n < 10; n++) {
            float4 hv = *(const float4*)&hbase[n * 132 + k4 * 4];
            acc[n] = fmaf(wv.x, hv.x, acc[n]);
            acc[n] = fmaf(wv.y, hv.y, acc[n]);
            acc[n] = fmaf(wv.z, hv.z, acc[n]);
            acc[n] = fmaf(wv.w, hv.w, acc[n]);
        }
    }
    int nodeBase = isU ? (b * 100 + n0 + half * 10) : (b * 200 + (n0 - 100) + half * 10);
    float* dst = isU ? (pu + (size_t)nodeBase * 128) : (pv + (size_t)nodeBase * 128);
    #pragma unroll
    for (int n = 0; n < 10; n++) dst[n * 128 + e] = acc[n];
}

// ---------------------------------------------------------------------------
// out[b,u,v,:] = mask*(pu[b,u,:] + pv[b,v,:]) + weights[b,u,v]*wl
// grid: 16 b * 9 balanced u-slices = 144 CTAs, 512 threads, streaming stores
// ---------------------------------------------------------------------------
__global__ void __launch_bounds__(512, 1) out_kernel(
    const float* __restrict__ pu, const float* __restrict__ pv,
    const void* __restrict__ adjraw, const float* __restrict__ weights,
    const float* __restrict__ Wlast, float* __restrict__ out)
{
    extern __shared__ float sm[];
    float* spv = sm;            // 200*128
    float* spu = sm + 25600;    // up to 12*128
    float* swl = sm + 27136;    // 128
    __shared__ int s_flags[2];

    const int b = blockIdx.x / 9, gslice = blockIdx.x % 9;
    const int u0 = (gslice * 100) / 9;
    const int u1 = ((gslice + 1) * 100) / 9;
    const int nu = u1 - u0;
    const int tid = threadIdx.x, lane = tid & 31, w = tid >> 5;

    const int mode = detect_adj_mode<512>(adjraw, s_flags);

    for (int i = tid; i < 6400; i += 512)
        ((float4*)spv)[i] = ((const float4*)(pv + b * 25600))[i];
    for (int i = tid; i < nu * 32; i += 512)
        ((float4*)spu)[i] = ((const float4*)(pu + (b * 100 + u0) * 128))[i];
    if (tid < 128) swl[tid] = Wlast[tid * 257 + 256];
    __syncthreads();

    const float4 wl4 = *(const float4*)&swl[lane * 4];
    for (int iu = 0; iu < nu; iu++) {
        const int u = u0 + iu;
        const int abase = (b * 100 + u) * 200;
        const float* wrow = weights + abase;
        const float4 pu4 = *(const float4*)&spu[iu * 128 + lane * 4];
        float* obase = out + ((size_t)(b * 100 + u)) * 200 * 128;
        for (int v = w; v < 200; v += 16) {
            float msk;
            if (mode == 0)      msk = ((const int*)adjraw)[abase + v] ? 0.f : 1.f;
            else if (mode == 1) msk = ((const unsigned char*)adjraw)[abase + v] ? 0.f : 1.f;
            else                msk = (((const float*)adjraw)[abase + v] != 0.f) ? 0.f : 1.f;
            const float wt  = wrow[v];
            const float4 pv4 = *(const float4*)&spv[v * 128 + lane * 4];
            float4 o;
            o.x = msk * (pu4.x + pv4.x) + wt * wl4.x;
            o.y = msk * (pu4.y + pv4.y) + wt * wl4.y;
            o.z = msk * (pu4.z + pv4.z) + wt * wl4.z;
            o.w = msk * (pu4.w + pv4.w) + wt * wl4.w;
            __stcs((float4*)&obase[(size_t)v * 128 + lane * 4], o);
        }
    }
}

// ---------------------------------------------------------------------------
extern "C" void kernel_launch(void* const* d_in, const int* in_sizes, int n_in,
                              void* d_out, int out_size)
{
    (void)in_sizes; (void)n_in; (void)out_size;
    const float* x              = (const float*)d_in[0];
    const void*  adj_raw        = (const void*)d_in[1];
    const float* weights        = (const float*)d_in[2];
    const float* Wlayers        = (const float*)d_in[3];
    const float* alayers        = (const float*)d_in[4];
    const float* Wlast          = (const float*)d_in[5];
    float* out = (float*)d_out;

    float *dH, *dpu, *dpv;
    cudaGetSymbolAddress((void**)&dH, g_hE);
    cudaGetSymbolAddress((void**)&dpu, g_pu);
    cudaGetSymbolAddress((void**)&dpv, g_pv);

    const int SM1 = 35072 * 4;                  // 140288
    const int SM2 = (2640 + 128 * 132) * 4;     // 78144
    const int SM3 = (27136 + 128) * 4;          // 109056
    cudaFuncSetAttribute(gat_fused_kernel, cudaFuncAttributeMaxDynamicSharedMemorySize, SM1);
    cudaFuncSetAttribute(pupv_kernel,      cudaFuncAttributeMaxDynamicSharedMemorySize, SM2);
    cudaFuncSetAttribute(out_kernel,       cudaFuncAttributeMaxDynamicSharedMemorySize, SM3);

    gat_fused_kernel<<<128, GAT_THREADS, SM1>>>(x, adj_raw, Wlayers, alayers, dH);
    pupv_kernel<<<240, 256, SM2>>>(dH, Wlast, dpu, dpv);
    out_kernel<<<144, 512, SM3>>>(dpu, dpv, adj_raw, weights, Wlast, out);
}

// round 9
// speedup vs baseline: 3.3376x; 1.0002x over previous
#include <cuda_runtime.h>
#include <cuda_bf16.h>
#include <math.h>

// B=16, N=300, U=100, V=200, E=128, H=8, hd=16, L=3
// out: [16, 20000, 128] f32 (163.8 MB)

// Scratch (allocation-free: device globals)
__device__ float g_hE[16 * 38400];
__device__ float g_pu[16 * 100 * 128];
__device__ float g_pv[16 * 200 * 128];

// ---------------------------------------------------------------------------
// adj dtype detection, inlined per consumer CTA. 2048-word window:
//   any word == 0x3F800000           -> float32
//   any word not in {0,1,0x3F800000} -> packed uint8 (p=0.3 -> certain)
//   else                             -> int32
// ---------------------------------------------------------------------------
template <int NT>
__device__ __forceinline__ int detect_adj_mode(const void* adjraw, int* s_flags)
{
    const unsigned int* aw = (const unsigned int*)adjraw;
    int tid = threadIdx.x;
    if (tid == 0) { s_flags[0] = 0; s_flags[1] = 0; }
    __syncthreads();
    int f32 = 0, multi = 0;
    #pragma unroll
    for (int i = tid; i < 2048; i += NT) {
        unsigned int v = aw[i];
        f32   |= (v == 0x3F800000u);
        multi |= (v != 0u && v != 1u && v != 0x3F800000u);
    }
    if (__any_sync(0xffffffffu, f32)   && (tid & 31) == 0) atomicOr(&s_flags[0], 1);
    if (__any_sync(0xffffffffu, multi) && (tid & 31) == 0) atomicOr(&s_flags[1], 1);
    __syncthreads();
    return s_flags[0] ? 2 : (s_flags[1] ? 1 : 0);   // 2=f32, 1=u8, 0=i32
}

// ---------------------------------------------------------------------------
// Fused 3-layer GAT: one CTA per (b, head). 1024 threads (32 warps).
// 2-row attention groups (register diet -> 64-reg / 32-warp occupancy).
// smem floats:
//   [0,4800)      sWh   [300][16]
//   [4800,9600)   shh   persistent h [300][16]
//   [9600,9856)   sWt   16x16 transposed
//   [9856,9872)   sa1   [9872,9888) sa2
//   [9888,10188)  se1[300]   [10188,10488) se2[300]
//   [10488,15488) sadj (20000 B, canonical u8)
//   [15488,28544) sattb [32 warps][2][204]
// total 114176 bytes -> 1 CTA/SM, 32 warps
// ---------------------------------------------------------------------------
#define GAT_THREADS 1024

__global__ void __launch_bounds__(GAT_THREADS, 1) gat_fused_kernel(
    const float* __restrict__ hin,
    const void*  __restrict__ adjraw,
    const float* __restrict__ Wl,   // [3][8][16][16]
    const float* __restrict__ al,   // [3][8][32]
    float* __restrict__ hout)
{
    extern __shared__ float sm[];
    float* sWh = sm;
    float* shh = sm + 4800;
    float* sWt = sm + 9600;
    float* sa1 = sm + 9856;
    float* sa2 = sm + 9872;
    float* se1 = sm + 9888;
    float* se2 = sm + 10188;
    unsigned char* sadj = (unsigned char*)(sm + 10488);
    float* sattb = sm + 15488;
    __shared__ int s_flags[2];

    const int tid  = threadIdx.x;
    const int lane = tid & 31;
    const int w    = tid >> 5;
    const int b    = blockIdx.x >> 3;
    const int hh   = blockIdx.x & 7;

    const float* hsrc = hin + (b * 8 + hh) * 4800;
    float* hdst = hout + (b * 8 + hh) * 4800;

    const int mode = detect_adj_mode<GAT_THREADS>(adjraw, s_flags);

    // ---- one-time loads ----
    for (int i = tid; i < 1200; i += GAT_THREADS)
        ((float4*)shh)[i] = ((const float4*)hsrc)[i];

    if (mode == 1) {
        const uint4* src = (const uint4*)((const unsigned char*)adjraw + b * 20000);
        for (int i = tid; i < 1250; i += GAT_THREADS)
            ((uint4*)sadj)[i] = src[i];
    } else if (mode == 0) {
        const int4* src = (const int4*)((const int*)adjraw + b * 20000);
        for (int i = tid; i < 5000; i += GAT_THREADS) {
            int4 v = src[i];
            ((uchar4*)sadj)[i] = make_uchar4(v.x != 0, v.y != 0, v.z != 0, v.w != 0);
        }
    } else {
        const float4* src = (const float4*)((const float*)adjraw + b * 20000);
        for (int i = tid; i < 5000; i += GAT_THREADS) {
            float4 v = src[i];
            ((uchar4*)sadj)[i] = make_uchar4(v.x != 0.f, v.y != 0.f, v.z != 0.f, v.w != 0.f);
        }
    }

    for (int l = 0; l < 3; l++) {
        const float* W = Wl + (l * 8 + hh) * 256;
        const float* a = al + (l * 8 + hh) * 32;
        if (tid < 256) {
            int j = tid >> 4, k = tid & 15;
            sWt[k * 16 + j] = W[tid];      // sWt[k][j] = W[j][k]
        }
        if (tid < 16) { sa1[tid] = a[tid]; sa2[tid] = a[16 + tid]; }
        __syncthreads();

        // ---- Wh = h @ W^T, e1 = Wh.a1, e2 = Wh.a2 ----
        for (int base = tid; base < 4800; base += GAT_THREADS) {
            int n = base >> 4, jj = base & 15;
            const float* hr = shh + n * 16;
            float s = 0.f;
            #pragma unroll
            for (int k = 0; k < 16; k++) s = fmaf(hr[k], sWt[k * 16 + jj], s);
            sWh[base] = s;
            float p1 = s * sa1[jj];
            float p2 = s * sa2[jj];
            #pragma unroll
            for (int off = 8; off; off >>= 1) {
                p1 += __shfl_xor_sync(0xffffffffu, p1, off);
                p2 += __shfl_xor_sync(0xffffffffu, p2, off);
            }
            if (jj == 0) { se1[n] = p1; se2[n] = p2; }
        }
        __syncthreads();

        // ---- attention: 150 groups of 2 rows (U:0..49, V:50..149), LPT ----
        for (int k = 0; k < 5; k++) {
            int g;
            if (k == 0)      g = w;                                    // U0..31
            else if (k == 1) g = (w < 14) ? (50 + w) : (32 + (w - 14)); // V0..13 / U32..49
            else if (k == 2) g = 64 + w;                               // V14..45
            else if (k == 3) g = 96 + w;                               // V46..77
            else { if (w >= 22) break; g = 128 + w; }                  // V78..99

            const bool modeU = (g < 50);
            const int  r0    = modeU ? (g << 1) : ((g - 50) << 1);

            float* ab = sattb + w * 408;
            float rowc[2], selfe[2];
            float ssum[2] = {0.f, 0.f};

            if (modeU) {
                #pragma unroll
                for (int r = 0; r < 2; r++) {
                    rowc[r]  = se1[r0 + r];
                    float t  = rowc[r] + se2[r0 + r];
                    selfe[r] = (t > 0.f) ? t : 0.01f * t;
                }
                const float* cb = se2 + 100;
                const unsigned char* adjU = sadj + r0 * 200;
                #pragma unroll
                for (int kk = 0; kk < 6; kk++) {
                    int idx = lane + (kk << 5);
                    float cv = cb[idx];
                    #pragma unroll
                    for (int r = 0; r < 2; r++) {
                        float t = rowc[r] + cv;
                        t = (t > 0.f) ? t : 0.01f * t;
                        float ev = __expf(t - selfe[r]);
                        ev = adjU[r * 200 + idx] ? 0.f : ev;
                        ab[r * 204 + idx] = ev;
                        ssum[r] += ev;
                    }
                }
                if (lane < 8) {                    // tail idx = 192+lane
                    int idx = 192 + lane;
                    float cv = cb[idx];
                    #pragma unroll
                    for (int r = 0; r < 2; r++) {
                        float t = rowc[r] + cv;
                        t = (t > 0.f) ? t : 0.01f * t;
                        float ev = __expf(t - selfe[r]);
                        ev = adjU[r * 200 + idx] ? 0.f : ev;
                        ab[r * 204 + idx] = ev;
                        ssum[r] += ev;
                    }
                }
            } else {
                #pragma unroll
                for (int r = 0; r < 2; r++) {
                    int node = 100 + r0 + r;
                    rowc[r]  = se2[node];
                    float t  = se1[node] + rowc[r];
                    selfe[r] = (t > 0.f) ? t : 0.01f * t;
                }
                const unsigned char* adjC = sadj + r0;
                #pragma unroll
                for (int kk = 0; kk < 3; kk++) {
                    int idx = lane + (kk << 5);
                    float cv = se1[idx];
                    unsigned int aw2 = *(const unsigned short*)(adjC + idx * 200);
                    #pragma unroll
                    for (int r = 0; r < 2; r++) {
                        float t = rowc[r] + cv;
                        t = (t > 0.f) ? t : 0.01f * t;
                        float ev = __expf(t - selfe[r]);
                        ev = ((aw2 >> (r * 8)) & 255u) ? 0.f : ev;
                        ab[r * 204 + idx] = ev;
                        ssum[r] += ev;
                    }
                }
                if (lane < 4) {                    // tail idx = 96+lane
                    int idx = 96 + lane;
                    float cv = se1[idx];
                    unsigned int aw2 = *(const unsigned short*)(adjC + idx * 200);
                    #pragma unroll
                    for (int r = 0; r < 2; r++) {
                        float t = rowc[r] + cv;
                        t = (t > 0.f) ? t : 0.01f * t;
                        float ev = __expf(t - selfe[r]);
                        ev = ((aw2 >> (r * 8)) & 255u) ? 0.f : ev;
                        ab[r * 204 + idx] = ev;
                        ssum[r] += ev;
                    }
                }
            }
            __syncwarp();

            // ssum tree (overlaps with aggregation latency below)
            #pragma unroll
            for (int off = 16; off; off >>= 1) {
                #pragma unroll
                for (int r = 0; r < 2; r++)
                    ssum[r] += __shfl_xor_sync(0xffffffffu, ssum[r], off);
            }
            float inv[2];
            #pragma unroll
            for (int r = 0; r < 2; r++)
                inv[r] = 1.f / (ssum[r] + 1.f);    // self term exp(0)=1

            // ---- aggregation over raw ev; normalize at the end ----
            const int q4 = (lane & 3) << 2, v4 = lane >> 2;
            float4 acc[2];
            #pragma unroll
            for (int r = 0; r < 2; r++) acc[r] = make_float4(0.f, 0.f, 0.f, 0.f);

            if (modeU) {
                const float* whb = sWh + 100 * 16 + q4;
                #pragma unroll 5
                for (int ii = 0; ii < 25; ii++) {
                    int i = v4 + (ii << 3);
                    float4 w4 = *(const float4*)&whb[i * 16];
                    #pragma unroll
                    for (int r = 0; r < 2; r++) {
                        float av = ab[r * 204 + i];
                        acc[r].x = fmaf(av, w4.x, acc[r].x);
                        acc[r].y = fmaf(av, w4.y, acc[r].y);
                        acc[r].z = fmaf(av, w4.z, acc[r].z);
                        acc[r].w = fmaf(av, w4.w, acc[r].w);
                    }
                }
            } else {
                const float* whb = sWh + q4;
                #pragma unroll 4
                for (int ii = 0; ii < 13; ii++) {
                    int i = v4 + (ii << 3);
                    if (i < 100) {
                        float4 w4 = *(const float4*)&whb[i * 16];
                        #pragma unroll
                        for (int r = 0; r < 2; r++) {
                            float av = ab[r * 204 + i];
                            acc[r].x = fmaf(av, w4.x, acc[r].x);
                            acc[r].y = fmaf(av, w4.y, acc[r].y);
                            acc[r].z = fmaf(av, w4.z, acc[r].z);
                            acc[r].w = fmaf(av, w4.w, acc[r].w);
                        }
                    }
                }
            }
            #pragma unroll
            for (int off = 4; off < 32; off <<= 1) {
                #pragma unroll
                for (int r = 0; r < 2; r++) {
                    acc[r].x += __shfl_xor_sync(0xffffffffu, acc[r].x, off);
                    acc[r].y += __shfl_xor_sync(0xffffffffu, acc[r].y, off);
                    acc[r].z += __shfl_xor_sync(0xffffffffu, acc[r].z, off);
                    acc[r].w += __shfl_xor_sync(0xffffffffu, acc[r].w, off);
                }
            }
            if (v4 == 0) {
                #pragma unroll
                for (int r = 0; r < 2; r++) {
                    int node = modeU ? (r0 + r) : (100 + r0 + r);
                    float4 ws = *(const float4*)&sWh[node * 16 + q4];
                    float4 res;
                    res.x = (acc[r].x + ws.x) * inv[r];
                    res.y = (acc[r].y + ws.y) * inv[r];
                    res.z = (acc[r].z + ws.z) * inv[r];
                    res.w = (acc[r].w + ws.w) * inv[r];
                    res.x = (res.x > 0.f) ? res.x : expm1f(res.x);
                    res.y = (res.y > 0.f) ? res.y : expm1f(res.y);
                    res.z = (res.z > 0.f) ? res.z : expm1f(res.z);
                    res.w = (res.w > 0.f) ? res.w : expm1f(res.w);
                    if (l == 2)
                        *(float4*)&hdst[node * 16 + q4] = res;
                    else
                        *(float4*)&shh[node * 16 + q4] = res;
                }
            }
            __syncwarp();
        }
        __syncthreads();   // shh fully written before next layer's Wh phase
    }
}

// ---------------------------------------------------------------------------
// pu = hE[:, :U] @ W1^T ; pv = hE[:, U:] @ W2^T
// ---------------------------------------------------------------------------
__global__ void __launch_bounds__(256, 1) pupv_kernel(
    const float* __restrict__ hE,
    const float* __restrict__ Wlast,  // [128][257]
    float* __restrict__ pu, float* __restrict__ pv)
{
    extern __shared__ float sm[];
    float* hsm = sm;           // 20*132
    float* Wsm = sm + 2640;    // 128*132

    const int blk = blockIdx.x;
    const int b = blk / 15, t = blk % 15;
    const bool isU = (t < 5);
    const int n0 = isU ? t * 20 : 100 + (t - 5) * 20;
    const int coff = isU ? 0 : 128;
    const int tid = threadIdx.x;

    for (int i = tid; i < 128 * 128; i += 256) {
        int e = i >> 7, k = i & 127;
        Wsm[e * 132 + k] = Wlast[e * 257 + coff + k];
    }
    for (int i = tid; i < 20 * 128; i += 256) {
        int n = i >> 7, k = i & 127;
        hsm[n * 132 + k] = hE[b * 38400 + (n0 + n) * 128 + k];
    }
    __syncthreads();

    const int e = tid & 127, half = tid >> 7;
    float acc[10];
    #pragma unroll
    for (int n = 0; n < 10; n++) acc[n] = 0.f;
    const float* wrow  = Wsm + e * 132;
    const float* hbase = hsm + (half * 10) * 132;

    #pragma unroll 8
    for (int k4 = 0; k4 < 32; k4++) {
        float4 wv = *(const float4*)&wrow[k4 * 4];
        #pragma unroll
        for (int n = 0; n < 10; n++) {
            float4 hv = *(const float4*)&hbase[n * 132 + k4 * 4];
            acc[n] = fmaf(wv.x, hv.x, acc[n]);
            acc[n] = fmaf(wv.y, hv.y, acc[n]);
            acc[n] = fmaf(wv.z, hv.z, acc[n]);
            acc[n] = fmaf(wv.w, hv.w, acc[n]);
        }
    }
    int nodeBase = isU ? (b * 100 + n0 + half * 10) : (b * 200 + (n0 - 100) + half * 10);
    float* dst = isU ? (pu + (size_t)nodeBase * 128) : (pv + (size_t)nodeBase * 128);
    #pragma unroll
    for (int n = 0; n < 10; n++) dst[n * 128 + e] = acc[n];
}

// ---------------------------------------------------------------------------
// out[b,u,v,:] = mask*(pu[b,u,:] + pv[b,v,:]) + weights[b,u,v]*wl
// grid: 16 b * 9 balanced u-slices = 144 CTAs, 512 threads, streaming stores
// ---------------------------------------------------------------------------
__global__ void __launch_bounds__(512, 1) out_kernel(
    const float* __restrict__ pu, const float* __restrict__ pv,
    const void* __restrict__ adjraw, const float* __restrict__ weights,
    const float* __restrict__ Wlast, float* __restrict__ out)
{
    extern __shared__ float sm[];
    float* spv = sm;            // 200*128
    float* spu = sm + 25600;    // up to 12*128
    float* swl = sm + 27136;    // 128
    __shared__ int s_flags[2];

    const int b = blockIdx.x / 9, gslice = blockIdx.x % 9;
    const int u0 = (gslice * 100) / 9;
    const int u1 = ((gslice + 1) * 100) / 9;
    const int nu = u1 - u0;
    const int tid = threadIdx.x, lane = tid & 31, w = tid >> 5;

    const int mode = detect_adj_mode<512>(adjraw, s_flags);

    for (int i = tid; i < 6400; i += 512)
        ((float4*)spv)[i] = ((const float4*)(pv + b * 25600))[i];
    for (int i = tid; i < nu * 32; i += 512)
        ((float4*)spu)[i] = ((const float4*)(pu + (b * 100 + u0) * 128))[i];
    if (tid < 128) swl[tid] = Wlast[tid * 257 + 256];
    __syncthreads();

    const float4 wl4 = *(const float4*)&swl[lane * 4];
    for (int iu = 0; iu < nu; iu++) {
        const int u = u0 + iu;
        const int abase = (b * 100 + u) * 200;
        const float* wrow = weights + abase;
        const float4 pu4 = *(const float4*)&spu[iu * 128 + lane * 4];
        float* obase = out + ((size_t)(b * 100 + u)) * 200 * 128;
        for (int v = w; v < 200; v += 16) {
            float msk;
            if (mode == 0)      msk = ((const int*)adjraw)[abase + v] ? 0.f : 1.f;
            else if (mode == 1) msk = ((const unsigned char*)adjraw)[abase + v] ? 0.f : 1.f;
            else                msk = (((const float*)adjraw)[abase + v] != 0.f) ? 0.f : 1.f;
            const float wt  = wrow[v];
            const float4 pv4 = *(const float4*)&spv[v * 128 + lane * 4];
            float4 o;
            o.x = msk * (pu4.x + pv4.x) + wt * wl4.x;
            o.y = msk * (pu4.y + pv4.y) + wt * wl4.y;
            o.z = msk * (pu4.z + pv4.z) + wt * wl4.z;
            o.w = msk * (pu4.w + pv4.w) + wt * wl4.w;
            __stcs((float4*)&obase[(size_t)v * 128 + lane * 4], o);
        }
    }
}

// ---------------------------------------------------------------------------
extern "C" void kernel_launch(void* const* d_in, const int* in_sizes, int n_in,
                              void* d_out, int out_size)
{
    (void)in_sizes; (void)n_in; (void)out_size;
    const float* x              = (const float*)d_in[0];
    const void*  adj_raw        = (const void*)d_in[1];
    const float* weights        = (const float*)d_in[2];
    const float* Wlayers        = (const float*)d_in[3];
    const float* alayers        = (const float*)d_in[4];
    const float* Wlast          = (const float*)d_in[5];
    float* out = (float*)d_out;

    float *dH, *dpu, *dpv;
    cudaGetSymbolAddress((void**)&dH, g_hE);
    cudaGetSymbolAddress((void**)&dpu, g_pu);
    cudaGetSymbolAddress((void**)&dpv, g_pv);

    const int SM1 = 28544 * 4;                  // 114176
    const int SM2 = (2640 + 128 * 132) * 4;     // 78144
    const int SM3 = (27136 + 128) * 4;          // 109056
    cudaFuncSetAttribute(gat_fused_kernel, cudaFuncAttributeMaxDynamicSharedMemorySize, SM1);
    cudaFuncSetAttribute(pupv_kernel,      cudaFuncAttributeMaxDynamicSharedMemorySize, SM2);
    cudaFuncSetAttribute(out_kernel,       cudaFuncAttributeMaxDynamicSharedMemorySize, SM3);

    gat_fused_kernel<<<128, GAT_THREADS, SM1>>>(x, adj_raw, Wlayers, alayers, dH);
    pupv_kernel<<<240, 256, SM2>>>(dH, Wlast, dpu, dpv);
    out_kernel<<<144, 512, SM3>>>(dpu, dpv, adj_raw, weights, Wlast, out);
}